// round 15
// baseline (speedup 1.0000x reference)
#include <cuda_runtime.h>
#include <cuda_bf16.h>
#include <math.h>
#include <stdint.h>

#define SQG 3.1464265445104548f   /* sqrt(NU-MU)=sqrt(9.9) */
#define SQ2 1.4142135623730951f
typedef __nv_bfloat16 bf16;

// ==================== device scratch ====================
__device__ float g_scale[9];
__device__ float g_part[9 * 64];
__device__ float g_Aq[2 * 1024 * 1024];   // two split-K planes
__device__ float g_Wq[1024 * 1024];
__device__ float g_Ar[7 * 512 * 512];
__device__ float g_Wr[8 * 512 * 512];
__device__ float g_CpanQ[1024 * 64];
__device__ float g_TQ[64 * 1024];
__device__ float g_CpanR[8 * 512 * 64];
__device__ float g_TR[8 * 64 * 512];
__device__ float g_Qm[4096 * 1024];
__device__ float g_Pm[8 * 512 * 512];
__device__ float g_Gs[7 * 512 * 512];
// bf16 hi/lo pairs
__device__ __align__(16) bf16 g_VTH[1024 * 3072],  g_VTL[1024 * 3072];
__device__ __align__(16) bf16 g_VH[3072 * 1024],   g_VL[3072 * 1024];
__device__ __align__(16) bf16 g_B2H[7 * 262144],   g_B2L[7 * 262144];
__device__ __align__(16) bf16 g_B2TH[7 * 262144],  g_B2TL[7 * 262144];
__device__ __align__(16) bf16 g_WqH[1024 * 1024],  g_WqL[1024 * 1024];
__device__ __align__(16) bf16 g_WqTH[1024 * 1024], g_WqTL[1024 * 1024];
__device__ __align__(16) bf16 g_WrH[8 * 262144],   g_WrL[8 * 262144];
__device__ __align__(16) bf16 g_WrTH[8 * 262144],  g_WrTL[8 * 262144];
__device__ __align__(16) bf16 g_ImAqTH[1024 * 1024], g_ImAqTL[1024 * 1024];
__device__ __align__(16) bf16 g_ImArTH[8 * 262144],  g_ImArTL[8 * 262144];
__device__ __align__(16) bf16 g_QmH[4096 * 1024],  g_QmL[4096 * 1024];
__device__ __align__(16) bf16 g_QmTH[1024 * 4096], g_QmTL[1024 * 4096];
__device__ __align__(16) bf16 g_PmH[8 * 262144],   g_PmL[8 * 262144];
__device__ __align__(16) bf16 g_PTH[8 * 262144],   g_PTL[8 * 262144];
__device__ __align__(16) bf16 g_GsH[7 * 262144],   g_GsL[7 * 262144];
__device__ __align__(16) bf16 g_GTH[7 * 262144],   g_GTL[7 * 262144];
__device__ __align__(16) bf16 g_xH[8192u * 1024u], g_xL[8192u * 1024u];
__device__ __align__(16) bf16 g_xhH[8192u * 4096u], g_xhL[8192u * 4096u];
__device__ __align__(16) bf16 g_actH[8192u * 512u], g_actL[8192u * 512u];
__device__ __align__(16) bf16 g_h0H[8192u * 512u],  g_h0L[8192u * 512u];
__device__ __align__(16) bf16 g_h1H[8192u * 512u],  g_h1L[8192u * 512u];
__device__ __align__(16) bf16 g_yhH[8192u * 4096u], g_yhL[8192u * 4096u];

// ==================== reductions ====================
__global__ void red_in(const float* Fq, const float* Fr0, const float* Frr) {
    __shared__ float sh[256];
    int z = blockIdx.y;
    const float* p; long n;
    if (z == 0)      { p = Fq;  n = 4096L * 1024; }
    else if (z == 1) { p = Fr0; n = 512L * 512; }
    else             { p = Frr + (long)(z - 2) * 512 * 1024; n = 512L * 1024; }
    float s = 0.f;
    for (long i = (long)blockIdx.x * 256 + threadIdx.x; i < n; i += 64L * 256) {
        float v = p[i]; s += v * v;
    }
    sh[threadIdx.x] = s; __syncthreads();
    for (int o = 128; o > 0; o >>= 1) {
        if (threadIdx.x < o) sh[threadIdx.x] += sh[threadIdx.x + o];
        __syncthreads();
    }
    if (threadIdx.x == 0) g_part[z * 64 + blockIdx.x] = sh[0];
}
__global__ void red_in_fin(const float* fq, const float* fr) {
    int t = threadIdx.x;
    if (t < 9) {
        float s = 0.f;
        for (int i = 0; i < 64; i++) s += g_part[t * 64 + i];
        float f = (t == 0) ? fq[0] : fr[t - 1];
        g_scale[t] = f / (sqrtf(s) + 1e-5f);
    }
}

// ==================== conversion kernels ====================
__device__ __forceinline__ void split_bf(float v, bf16& h, bf16& l) {
    h = __float2bfloat16_rn(v);
    l = __float2bfloat16_rn(v - __bfloat162float(h));
}
__global__ void cvt_k(const float* src, int ldS, long sS,
                      bf16* hi, bf16* lo, int ldD, long sD) {
    int z = blockIdx.z;
    src += (long)z * sS; hi += (long)z * sD; lo += (long)z * sD;
    int r = blockIdx.y, c = blockIdx.x * 256 + threadIdx.x;
    bf16 h, l;
    split_bf(src[(long)r * ldS + c], h, l);
    hi[(long)r * ldD + c] = h;
    lo[(long)r * ldD + c] = l;
}
__global__ void tr_cvt(const float* src, int ldS, long sS,
                       bf16* hi, bf16* lo, int ldD, long sD) {
    int z = blockIdx.z;
    src += (long)z * sS; hi += (long)z * sD; lo += (long)z * sD;
    __shared__ float t[32][33];
    int r0 = blockIdx.y * 32, c0 = blockIdx.x * 32;
    int tx = threadIdx.x & 31, ty = threadIdx.x >> 5;
    for (int i = ty; i < 32; i += 8) t[i][tx] = src[(long)(r0 + i) * ldS + c0 + tx];
    __syncthreads();
    for (int i = ty; i < 32; i += 8) {
        bf16 h, l;
        split_bf(t[tx][i], h, l);
        hi[(long)(c0 + i) * ldD + r0 + tx] = h;
        lo[(long)(c0 + i) * ldD + r0 + tx] = l;
    }
}

// ==================== elementwise prep ====================
__global__ void prepQ(const float* Fq) {
    int e = blockIdx.x * 256 + threadIdx.x;
    int i = e >> 10, j = e & 1023;
    float s = g_scale[0];
    float a = g_Aq[e] + g_Aq[e + 1048576]
            + s * (Fq[i * 1024 + j] - Fq[j * 1024 + i]);
    float d = (i == j) ? 1.f : 0.f;
    g_Wq[e] = d + a;
    bf16 h, l;
    split_bf(d - a, h, l);
    g_ImAqTH[j * 1024 + i] = h;
    g_ImAqTL[j * 1024 + i] = l;
}
__global__ void prepR(const float* Fr0, const float* Frr) {
    int e = blockIdx.x * 256 + threadIdx.x;
    int z = e >> 18; int r = e & 262143;
    int i = r >> 9, j = r & 511;
    float a;
    if (z == 0) {
        float s = g_scale[1];
        a = s * (Fr0[i * 512 + j] - Fr0[j * 512 + i]);
    } else {
        float s = g_scale[1 + z];
        const float* B = Frr + (long)(z - 1) * 524288;
        a = g_Ar[(long)(z - 1) * 262144 + r] + s * (B[j * 1024 + i] - B[i * 1024 + j]);
    }
    float d = (i == j) ? 1.f : 0.f;
    g_Wr[e] = d + a;
    bf16 h, l;
    split_bf(d - a, h, l);
    g_ImArTH[z * 262144 + j * 512 + i] = h;
    g_ImArTL[z * 262144 + j * 512 + i] = l;
}

// ==================== blocked in-place Gauss-Jordan (block 64) ====================
__device__ void gj_rowx_body(const float* W, int n, int s, int jb,
                             float* T, float* Cpan) {
    int t = threadIdx.x;
    for (int e = t; e < 4096; e += 256) {
        int i = e >> 6, c = e & 63;
        Cpan[(long)(jb * 64 + i) * 64 + c] = W[(long)(jb * 64 + i) * n + s * 64 + c];
    }
    __shared__ float sh[64][65];
    __shared__ float shW[64][65];
    for (int e = t; e < 4096; e += 256) {
        int i = e >> 6, j = e & 63;
        sh[i][j] = W[(long)(s * 64 + i) * n + s * 64 + j];
        if (jb != s)
            shW[i][j] = W[(long)(s * 64 + i) * n + jb * 64 + j];
    }
    __syncthreads();
    int jc = t & 63, rb = (t >> 6) * 16;
    for (int p = 0; p < 64; p++) {
        float d = 1.0f / sh[p][p];
        float c[16];
#pragma unroll
        for (int r = 0; r < 16; r++) c[r] = sh[rb + r][p];
        float pv = sh[p][jc];
        __syncthreads();
        float npv = (jc == p) ? d : pv * d;
#pragma unroll
        for (int r = 0; r < 16; r++) {
            int i = rb + r;
            if (i == p)       sh[i][jc] = npv;
            else if (jc == p) sh[i][jc] = -c[r] * d;
            else              sh[i][jc] = sh[i][jc] - c[r] * npv;
        }
        __syncthreads();
    }
    if (jb == s) {
        for (int e = t; e < 4096; e += 256)
            T[(long)(e >> 6) * n + s * 64 + (e & 63)] = sh[e >> 6][e & 63];
        return;
    }
    float acc[16];
#pragma unroll
    for (int r = 0; r < 16; r++) acc[r] = 0.f;
    for (int k = 0; k < 64; k++) {
        float bv = shW[k][jc];
#pragma unroll
        for (int r = 0; r < 16; r++) acc[r] = fmaf(sh[rb + r][k], bv, acc[r]);
    }
#pragma unroll
    for (int r = 0; r < 16; r++)
        T[(long)(rb + r) * n + jb * 64 + jc] = acc[r];
}
__device__ void gj_upd_body(float* W, int n, int s, int jb, int ib,
                            const float* Cpan, const float* T) {
    int t = threadIdx.x;
    if (ib == s) {
        for (int e = t; e < 4096; e += 256) {
            int i = e >> 6, j = e & 63;
            W[(long)(s * 64 + i) * n + jb * 64 + j] = T[(long)i * n + jb * 64 + j];
        }
        return;
    }
    __shared__ float shC[64][65], shT[64][65];
    for (int e = t; e < 4096; e += 256) {
        int i = e >> 6, j = e & 63;
        shC[i][j] = Cpan[(long)(ib * 64 + i) * 64 + j];
        shT[i][j] = T[(long)i * n + jb * 64 + j];
    }
    __syncthreads();
    int jc = t & 63, rb = (t >> 6) * 16;
    float acc[16];
#pragma unroll
    for (int r = 0; r < 16; r++) acc[r] = 0.f;
    for (int k = 0; k < 64; k++) {
        float tv = shT[k][jc];
#pragma unroll
        for (int r = 0; r < 16; r++) acc[r] = fmaf(shC[rb + r][k], tv, acc[r]);
    }
#pragma unroll
    for (int r = 0; r < 16; r++) {
        long idx = (long)(ib * 64 + rb + r) * n + jb * 64 + jc;
        float oldv = (jb == s) ? 0.f : W[idx];
        W[idx] = oldv - acc[r];
    }
}
__global__ void cgj_rowx(const float* WQ, const float* WR, int s,
                         float* TQp, float* TRp, float* CQ, float* CR) {
    int z = blockIdx.y, jb = blockIdx.x;
    if (z == 0) { gj_rowx_body(WQ, 1024, s, jb, TQp, CQ); return; }
    if (s >= 8 || jb >= 8) return;
    gj_rowx_body(WR + (long)(z - 1) * 262144, 512, s, jb,
                 TRp + (long)(z - 1) * 32768, CR + (long)(z - 1) * 32768);
}
__global__ void cgj_upd(float* WQ, float* WR, int s,
                        const float* CQ, const float* CR,
                        const float* TQp, const float* TRp) {
    int z = blockIdx.z, jb = blockIdx.x, ib = blockIdx.y;
    if (z == 0) { gj_upd_body(WQ, 1024, s, jb, ib, CQ, TQp); return; }
    if (s >= 8 || jb >= 8 || ib >= 8) return;
    gj_upd_body(WR + (long)(z - 1) * 262144, 512, s, jb, ib,
                CR + (long)(z - 1) * 32768, TRp + (long)(z - 1) * 32768);
}

// ==================== mma.sync bf16 GEMM (3-stage, swizzled smem) ============
struct TCP {
    const bf16 *AH0, *AL0, *AH1, *AL1, *BH0, *BL0, *BH1, *BL1;
    const float *S1, *bias;
    const bf16 *S1H, *S1L;
    float* C;
    bf16 *CH, *CL;
    int lda0, lda1, ldb0, ldb1, ldc, ld1;
    long sA, sB, sC;
    int kChunks, kSplitCh;
    int epi;                    // 0 plain | 2 relu+bias | 3 -S1 | 4 S1- | 5 final
    int sIdx, sStride, sPow;
    float alpha, c1;
    int nSplit;
    int epiB, ld1B, ldcB;
    const float* S1B;
    const bf16 *S1BH, *S1BL;
    float* CB;
    bf16 *CHB, *CLB;
};
#define MM_STAGE 32768
#define MM_SMEM (3 * MM_STAGE)   /* 98304 */

__device__ __forceinline__ uint32_t smem_u32(const void* p) {
    uint32_t a;
    asm("{ .reg .u64 t; cvta.to.shared.u64 t, %1; cvt.u32.u64 %0, t; }"
        : "=r"(a) : "l"(p));
    return a;
}
__device__ __forceinline__ uint32_t swz(int row, int col) {
    return (uint32_t)((row << 6) + ((((col >> 3) ^ ((row >> 1) & 3)) << 4)));
}
__device__ __forceinline__ void cp16(uint32_t s, const void* g) {
    asm volatile("cp.async.cg.shared.global [%0], [%1], 16;" :: "r"(s), "l"(g));
}
__device__ __forceinline__ void cp_commit() {
    asm volatile("cp.async.commit_group;");
}
template <int N>
__device__ __forceinline__ void cp_wait() {
    asm volatile("cp.async.wait_group %0;" :: "n"(N));
}
__device__ __forceinline__ void ldsm4(uint32_t* r, uint32_t addr) {
    asm volatile("ldmatrix.sync.aligned.m8n8.x4.shared.b16 {%0,%1,%2,%3}, [%4];"
        : "=r"(r[0]), "=r"(r[1]), "=r"(r[2]), "=r"(r[3]) : "r"(addr));
}
__device__ __forceinline__ void mma_bf16(float* d, const uint32_t* a, const uint32_t* b) {
    asm volatile(
        "mma.sync.aligned.m16n8k16.row.col.f32.bf16.bf16.f32 "
        "{%0,%1,%2,%3},{%4,%5,%6,%7},{%8,%9},{%0,%1,%2,%3};"
        : "+f"(d[0]), "+f"(d[1]), "+f"(d[2]), "+f"(d[3])
        : "r"(a[0]), "r"(a[1]), "r"(a[2]), "r"(a[3]), "r"(b[0]), "r"(b[1]));
}
__device__ __forceinline__ float s1_pair(const bf16* H, const bf16* L, long off,
                                         float& v1out) {
    uint32_t hw = *(const uint32_t*)(H + off);
    uint32_t lw = *(const uint32_t*)(L + off);
    __nv_bfloat162 hb = *(__nv_bfloat162*)&hw;
    __nv_bfloat162 lb = *(__nv_bfloat162*)&lw;
    v1out = __bfloat162float(hb.y) + __bfloat162float(lb.y);
    return __bfloat162float(hb.x) + __bfloat162float(lb.x);
}

__global__ void __launch_bounds__(256, 2) mma_gemm(TCP p) {
    extern __shared__ bf16 sm[];
    uint32_t sbase = smem_u32(sm);
    int tid = threadIdx.x, lane = tid & 31, wid = tid >> 5;
    int wm = wid & 3, wn = wid >> 2;
    int bm = blockIdx.y * 128, bn = blockIdx.x * 128;
    int z = blockIdx.z;
    const bf16* AH0z = p.AH0 + (long)z * p.sA;
    const bf16* AL0z = p.AL0 + (long)z * p.sA;

    const bf16* BH = p.BH0 + (long)z * p.sB;
    const bf16* BL = p.BL0 + (long)z * p.sB;
    int ldbN = p.ldb0;
    int bnB = bn;
    int half2 = 0;
    if (p.nSplit > 0 && bn >= p.nSplit) {
        half2 = 1; bnB = bn - p.nSplit;
        BH = p.BH1; BL = p.BL1; ldbN = p.ldb1;
    }

    float acc[2][8][4];
#pragma unroll
    for (int i = 0; i < 2; i++)
#pragma unroll
        for (int j = 0; j < 8; j++)
#pragma unroll
            for (int q = 0; q < 4; q++) acc[i][j][q] = 0.f;

    auto gissue = [&](int c, int stg) {
        const bf16 *Ah, *Al, *Bh, *Bl; int lda, ldb2, kk, kb;
        if (c < p.kSplitCh) {
            Ah = AH0z; Al = AL0z; lda = p.lda0; kk = c * 32;
            Bh = BH; Bl = BL; ldb2 = ldbN; kb = c * 32;
        } else {
            Ah = p.AH1; Al = p.AL1; lda = p.lda1; kk = (c - p.kSplitCh) * 32;
            Bh = p.BH1; Bl = p.BL1; ldb2 = p.ldb1; kb = kk;
        }
        uint32_t s0 = sbase + stg * MM_STAGE;
#pragma unroll
        for (int j = 0; j < 8; j++) {
            int li = tid + 256 * j;
            int m = li >> 9;
            int idx = li & 511;
            int row = idx >> 2, co = (idx & 3) << 3;
            const bf16* g;
            if (m == 0)      g = Ah + (long)(bm + row) * lda + kk + co;
            else if (m == 1) g = Al + (long)(bm + row) * lda + kk + co;
            else if (m == 2) g = Bh + (long)(bnB + row) * ldb2 + kb + co;
            else             g = Bl + (long)(bnB + row) * ldb2 + kb + co;
            cp16(s0 + m * 8192 + swz(row, co), g);
        }
        cp_commit();
    };
    auto compute = [&](int stg) {
        uint32_t s0 = sbase + stg * MM_STAGE;
        int arow = wm * 32 + (lane & 15);
        int acol = (lane >> 4) << 3;
        int brow = wn * 64 + (lane & 7) + ((lane & 16) >> 1);
        int bcol = lane & 8;
        // ks=0 fragments
        uint32_t Ah0[2][4], Al0[2][4], Bh0[4][4], Bl0[4][4];
        // ks=1 fragments
        uint32_t Ah1[2][4], Al1[2][4], Bh1[4][4], Bl1[4][4];

        // ldsm A0h + B0h
#pragma unroll
        for (int mt = 0; mt < 2; mt++)
            ldsm4(Ah0[mt], s0 + swz(arow + mt * 16, acol));
#pragma unroll
        for (int g = 0; g < 4; g++)
            ldsm4(Bh0[g], s0 + 16384 + swz(brow + g * 16, bcol));
        // hh0
#pragma unroll
        for (int mt = 0; mt < 2; mt++)
#pragma unroll
            for (int nt = 0; nt < 8; nt++)
                mma_bf16(acc[mt][nt], Ah0[mt], &Bh0[nt >> 1][(nt & 1) * 2]);
        // ldsm B0l (under hh0 drain)
#pragma unroll
        for (int g = 0; g < 4; g++)
            ldsm4(Bl0[g], s0 + 24576 + swz(brow + g * 16, bcol));
        // hl0
#pragma unroll
        for (int mt = 0; mt < 2; mt++)
#pragma unroll
            for (int nt = 0; nt < 8; nt++)
                mma_bf16(acc[mt][nt], Ah0[mt], &Bl0[nt >> 1][(nt & 1) * 2]);
        // ldsm A0l + prefetch ks=1 A1h,B1h (under hl0 drain)
#pragma unroll
        for (int mt = 0; mt < 2; mt++)
            ldsm4(Al0[mt], s0 + 8192 + swz(arow + mt * 16, acol));
#pragma unroll
        for (int mt = 0; mt < 2; mt++)
            ldsm4(Ah1[mt], s0 + swz(arow + mt * 16, 16 + acol));
#pragma unroll
        for (int g = 0; g < 4; g++)
            ldsm4(Bh1[g], s0 + 16384 + swz(brow + g * 16, 16 + bcol));
        // lh0
#pragma unroll
        for (int mt = 0; mt < 2; mt++)
#pragma unroll
            for (int nt = 0; nt < 8; nt++)
                mma_bf16(acc[mt][nt], Al0[mt], &Bh0[nt >> 1][(nt & 1) * 2]);
        // hh1
#pragma unroll
        for (int mt = 0; mt < 2; mt++)
#pragma unroll
            for (int nt = 0; nt < 8; nt++)
                mma_bf16(acc[mt][nt], Ah1[mt], &Bh1[nt >> 1][(nt & 1) * 2]);
        // ldsm B1l
#pragma unroll
        for (int g = 0; g < 4; g++)
            ldsm4(Bl1[g], s0 + 24576 + swz(brow + g * 16, 16 + bcol));
        // hl1
#pragma unroll
        for (int mt = 0; mt < 2; mt++)
#pragma unroll
            for (int nt = 0; nt < 8; nt++)
                mma_bf16(acc[mt][nt], Ah1[mt], &Bl1[nt >> 1][(nt & 1) * 2]);
        // ldsm A1l
#pragma unroll
        for (int mt = 0; mt < 2; mt++)
            ldsm4(Al1[mt], s0 + 8192 + swz(arow + mt * 16, 16 + acol));
        // lh1
#pragma unroll
        for (int mt = 0; mt < 2; mt++)
#pragma unroll
            for (int nt = 0; nt < 8; nt++)
                mma_bf16(acc[mt][nt], Al1[mt], &Bh1[nt >> 1][(nt & 1) * 2]);
    };

    gissue(0, 0);
    if (p.kChunks > 1) gissue(1, 1);
    for (int c = 0; c < p.kChunks; ++c) {
        if (c + 1 < p.kChunks) cp_wait<1>(); else cp_wait<0>();
        __syncthreads();
        if (c + 2 < p.kChunks) gissue(c + 2, (c + 2) % 3);
        compute(c % 3);
    }

    float al = p.alpha;
    if (p.sIdx >= 0) {
        float s = g_scale[p.sIdx + z * p.sStride];
        al *= (p.sPow == 2) ? s * s : s;
    }
    int epi = half2 ? p.epiB : p.epi;
    int ld1 = half2 ? p.ld1B : p.ld1;
    int ldc = half2 ? p.ldcB : p.ldc;
    const float* S1F = half2 ? p.S1B : p.S1;
    const bf16* S1H = half2 ? p.S1BH : p.S1H;
    const bf16* S1L = half2 ? p.S1BL : p.S1L;
    float* Cz  = half2 ? p.CB  : (p.C  ? p.C  + (long)z * p.sC : (float*)0);
    bf16* CHz  = half2 ? p.CHB : (p.CH ? p.CH + (long)z * p.sC : (bf16*)0);
    bf16* CLz  = half2 ? p.CLB : (p.CL ? p.CL + (long)z * p.sC : (bf16*)0);
    int nOff = half2 ? p.nSplit : 0;
#pragma unroll
    for (int mt = 0; mt < 2; mt++) {
#pragma unroll
        for (int nt = 0; nt < 8; nt++) {
            int r0 = bm + wm * 32 + mt * 16 + (lane >> 2);
            int c0 = bn + wn * 64 + nt * 8 + (lane & 3) * 2 - nOff;
#pragma unroll
            for (int h = 0; h < 2; h++) {
                int r = r0 + h * 8;
                float v0 = al * acc[mt][nt][h * 2 + 0];
                float v1 = al * acc[mt][nt][h * 2 + 1];
                if (epi == 2) {
                    v0 = fmaxf(v0 + p.bias[c0], 0.f);
                    v1 = fmaxf(v1 + p.bias[c0 + 1], 0.f);
                } else if (epi == 3) {
                    float s1b, s1a = s1_pair(S1H, S1L, (long)r * ld1 + c0, s1b);
                    v0 -= s1a; v1 -= s1b;
                } else if (epi == 4) {
                    float s1b, s1a = s1_pair(S1H, S1L, (long)r * ld1 + c0, s1b);
                    v0 = s1a - v0; v1 = s1b - v1;
                } else if (epi == 5) {
                    v0 = v0 + p.c1 * S1F[(long)r * ld1 + c0] + p.bias[c0];
                    v1 = v1 + p.c1 * S1F[(long)r * ld1 + c0 + 1] + p.bias[c0 + 1];
                }
                if (Cz) {
                    float2 o; o.x = v0; o.y = v1;
                    *(float2*)(Cz + (long)r * ldc + c0) = o;
                }
                if (CHz) {
                    __nv_bfloat162 hh = __floats2bfloat162_rn(v0, v1);
                    float rx = v0 - __bfloat162float(hh.x);
                    float ry = v1 - __bfloat162float(hh.y);
                    __nv_bfloat162 ll = __floats2bfloat162_rn(rx, ry);
                    *(uint32_t*)(CHz + (long)r * ldc + c0) = *(uint32_t*)&hh;
                    *(uint32_t*)(CLz + (long)r * ldc + c0) = *(uint32_t*)&ll;
                }
            }
        }
    }
}

// ==================== host ====================
static TCP mkT() {
    TCP t; memset(&t, 0, sizeof(t));
    t.sIdx = -1; t.alpha = 1.f;
    return t;
}
static void TCG(const TCP& p, int M, int N, int batch = 1) {
    dim3 g(N / 128, M / 128, batch);
    mma_gemm<<<g, 256, MM_SMEM>>>(p);
}
static float* sym(const void* s) {
    void* ptr = nullptr;
    cudaGetSymbolAddress(&ptr, s);
    return (float*)ptr;
}
static bf16* symb(const void* s) {
    void* ptr = nullptr;
    cudaGetSymbolAddress(&ptr, s);
    return (bf16*)ptr;
}

extern "C" void kernel_launch(void* const* d_in, const int* in_sizes, int n_in,
                              void* d_out, int out_size) {
    const float* x   = (const float*)d_in[0];
    const float* Fq  = (const float*)d_in[1];
    const float* fq  = (const float*)d_in[2];
    const float* by  = (const float*)d_in[3];
    const float* Fr0 = (const float*)d_in[4];
    const float* Frr = (const float*)d_in[5];
    const float* fr  = (const float*)d_in[6];
    const float* b   = (const float*)d_in[7];
    float* out = (float*)d_out;

    cudaFuncSetAttribute(mma_gemm, cudaFuncAttributeMaxDynamicSharedMemorySize, MM_SMEM);

    float* Aq  = sym(g_Aq);   float* Wq  = sym(g_Wq);
    float* Arr = sym(g_Ar);   float* Wr  = sym(g_Wr);
    float* CpanQ = sym(g_CpanQ); float* TQ = sym(g_TQ);
    float* CpanR = sym(g_CpanR); float* TR = sym(g_TR);
    float* Qm = sym(g_Qm); float* Pm = sym(g_Pm); float* Gsm = sym(g_Gs);
    bf16 *VTH = symb(g_VTH), *VTL = symb(g_VTL), *VH = symb(g_VH), *VL = symb(g_VL);
    bf16 *B2H = symb(g_B2H), *B2L = symb(g_B2L), *B2TH = symb(g_B2TH), *B2TL = symb(g_B2TL);
    bf16 *WqH = symb(g_WqH), *WqL = symb(g_WqL), *WqTH = symb(g_WqTH), *WqTL = symb(g_WqTL);
    bf16 *WrH = symb(g_WrH), *WrL = symb(g_WrL), *WrTH = symb(g_WrTH), *WrTL = symb(g_WrTL);
    bf16 *ImAqTH = symb(g_ImAqTH), *ImAqTL = symb(g_ImAqTL);
    bf16 *ImArTH = symb(g_ImArTH), *ImArTL = symb(g_ImArTL);
    bf16 *QmH = symb(g_QmH), *QmL = symb(g_QmL), *QmTH = symb(g_QmTH), *QmTL = symb(g_QmTL);
    bf16 *PmH = symb(g_PmH), *PmL = symb(g_PmL), *PTH = symb(g_PTH), *PTL = symb(g_PTL);
    bf16 *GsH = symb(g_GsH), *GsL = symb(g_GsL), *GTH = symb(g_GTH), *GTL = symb(g_GTL);
    bf16 *xH = symb(g_xH), *xL = symb(g_xL);
    bf16 *xhH = symb(g_xhH), *xhL = symb(g_xhL);
    bf16 *actH = symb(g_actH), *actL = symb(g_actL);
    bf16 *h0H = symb(g_h0H), *h0L = symb(g_h0L);
    bf16 *h1H = symb(g_h1H), *h1L = symb(g_h1L);
    bf16 *yhH = symb(g_yhH), *yhL = symb(g_yhL);

    // ---- scales ----
    red_in<<<dim3(64, 9), 256>>>(Fq, Fr0, Frr);
    red_in_fin<<<1, 32>>>(fq, fr);

    // ---- input conversions ----
    tr_cvt<<<dim3(32, 96), 256>>>(Fq + 1048576, 1024, 0, VTH, VTL, 3072, 0);

    // ---- Aq = s0^2 * VT @ VT' (split-K x2) ----
    { TCP t = mkT();
      t.AH0 = VTH; t.AL0 = VTL; t.lda0 = 3072; t.sA = 1536;
      t.BH0 = VTH; t.BL0 = VTL; t.ldb0 = 3072; t.sB = 1536;
      t.C = Aq; t.ldc = 1024; t.sC = 1048576;
      t.kChunks = 48; t.kSplitCh = 48;
      t.sIdx = 0; t.sStride = 0; t.sPow = 2; TCG(t, 1024, 1024, 2); }

    // ---- remaining input conversions ----
    cvt_k<<<dim3(2, 512, 7), 256>>>(Frr + 512, 1024, 524288, B2H, B2L, 512, 262144);
    tr_cvt<<<dim3(16, 16, 7), 256>>>(Frr + 512, 1024, 524288, B2TH, B2TL, 512, 262144);
    { TCP t = mkT();   // Ar_z = s^2 * B2 B2^T
      t.AH0 = B2H; t.AL0 = B2L; t.lda0 = 512; t.sA = 262144;
      t.BH0 = B2H; t.BL0 = B2L; t.ldb0 = 512; t.sB = 262144;
      t.C = Arr; t.ldc = 512; t.sC = 262144; t.kChunks = 16; t.kSplitCh = 16;
      t.sIdx = 2; t.sStride = 1; t.sPow = 2; TCG(t, 512, 512, 7); }
    cvt_k<<<dim3(4, 3072), 256>>>(Fq + 1048576, 1024, 0, VH, VL, 1024, 0);
    cvt_k<<<dim3(4, 8192), 256>>>(x, 1024, 0, xH, xL, 1024, 0);

    prepQ<<<4096, 256>>>(Fq);
    prepR<<<8192, 256>>>(Fr0, Frr);

    // ---- inversions (2 launches per step) ----
    for (int s = 0; s < 16; s++) {
        cgj_rowx<<<dim3(16, 9), 256>>>(Wq, Wr, s, TQ, TR, CpanQ, CpanR);
        cgj_upd<<<dim3(16, 16, 9), 256>>>(Wq, Wr, s, CpanQ, CpanR, TQ, TR);
    }
    cvt_k<<<dim3(4, 1024), 256>>>(Wq, 1024, 0, WqH, WqL, 1024, 0);
    tr_cvt<<<dim3(32, 32), 256>>>(Wq, 1024, 0, WqTH, WqTL, 1024, 0);
    cvt_k<<<dim3(2, 512, 8), 256>>>(Wr, 512, 262144, WrH, WrL, 512, 262144);
    tr_cvt<<<dim3(16, 16, 8), 256>>>(Wr, 512, 262144, WrTH, WrTL, 512, 262144);

    // ---- assemble Q / P / Gs ----
    { TCP t = mkT();   // Qm top = Winv @ (I-A)
      t.AH0 = WqH; t.AL0 = WqL; t.lda0 = 1024;
      t.BH0 = ImAqTH; t.BL0 = ImAqTL; t.ldb0 = 1024;
      t.C = Qm; t.CH = QmH; t.CL = QmL; t.ldc = 1024;
      t.kChunks = 32; t.kSplitCh = 32; TCG(t, 1024, 1024); }
    { TCP t = mkT();   // Qm bottom = -2 s0 * V @ Winv
      t.AH0 = VH; t.AL0 = VL; t.lda0 = 1024;
      t.BH0 = WqTH; t.BL0 = WqTL; t.ldb0 = 1024;
      t.C = Qm + 1048576; t.CH = QmH + 1048576; t.CL = QmL + 1048576; t.ldc = 1024;
      t.kChunks = 32; t.kSplitCh = 32;
      t.sIdx = 0; t.sStride = 0; t.sPow = 1; t.alpha = -2.f; TCG(t, 3072, 1024); }
    { TCP t = mkT();   // P_z = Winv_z @ (I-A_z)
      t.AH0 = WrH; t.AL0 = WrL; t.lda0 = 512; t.sA = 262144;
      t.BH0 = ImArTH; t.BL0 = ImArTL; t.ldb0 = 512; t.sB = 262144;
      t.C = Pm; t.CH = PmH; t.CL = PmL; t.ldc = 512; t.sC = 262144;
      t.kChunks = 16; t.kSplitCh = 16; TCG(t, 512, 512, 8); }
    { TCP t = mkT();   // Gs_z = -2 s * B2^T @ Winv_{z+1}
      t.AH0 = B2TH; t.AL0 = B2TL; t.lda0 = 512; t.sA = 262144;
      t.BH0 = WrTH + 262144; t.BL0 = WrTL + 262144; t.ldb0 = 512; t.sB = 262144;
      t.C = Gsm; t.CH = GsH; t.CL = GsL; t.ldc = 512; t.sC = 262144;
      t.kChunks = 16; t.kSplitCh = 16;
      t.sIdx = 2; t.sStride = 1; t.sPow = 1; t.alpha = -2.f; TCG(t, 512, 512, 7); }

    tr_cvt<<<dim3(32, 128), 256>>>(Qm, 1024, 0, QmTH, QmTL, 4096, 0);
    tr_cvt<<<dim3(16, 16, 8), 256>>>(Pm, 512, 262144, PTH, PTL, 512, 262144);
    tr_cvt<<<dim3(16, 16, 7), 256>>>(Gsm, 512, 262144, GTH, GTL, 512, 262144);

    // ---- forward pass ----
    { TCP t = mkT();   // xh = SQG * x @ Q^T
      t.AH0 = xH; t.AL0 = xL; t.lda0 = 1024;
      t.BH0 = QmH; t.BL0 = QmL; t.ldb0 = 1024;
      t.CH = xhH; t.CL = xhL; t.ldc = 4096;
      t.kChunks = 32; t.kSplitCh = 32;
      t.epi = 0; t.alpha = SQG; TCG(t, 8192, 4096); }
    { TCP t = mkT();   // act = relu(SQ2 * xk @ P0' + b0)
      t.AH0 = xhH; t.AL0 = xhL; t.lda0 = 4096;
      t.BH0 = PmH; t.BL0 = PmL; t.ldb0 = 512;
      t.CH = actH; t.CL = actL; t.ldc = 512;
      t.kChunks = 16; t.kSplitCh = 16;
      t.epi = 2; t.alpha = SQ2; t.bias = b; TCG(t, 8192, 512); }
    { TCP t = mkT();   // h0 = SQ2 * act @ P0 - xk
      t.AH0 = actH; t.AL0 = actL; t.lda0 = 512;
      t.BH0 = PTH; t.BL0 = PTL; t.ldb0 = 512;
      t.CH = h0H; t.CL = h0L; t.ldc = 512;
      t.kChunks = 16; t.kSplitCh = 16;
      t.epi = 3; t.S1H = xhH; t.S1L = xhL; t.ld1 = 4096;
      t.alpha = SQ2; TCG(t, 8192, 512); }

    bf16* hbH[2] = {h0H, h1H};
    bf16* hbL[2] = {h0L, h1L};
    for (int k = 1; k < 8; k++) {
        bf16* hpH = hbH[(k + 1) & 1];
        bf16* hpL = hbL[(k + 1) & 1];
        bf16* hnH = hbH[k & 1];
        bf16* hnL = hbL[k & 1];
        { TCP t = mkT();   // pre = relu(SQ2*(xk@P' + hp@G') + bk)
          t.AH0 = xhH + k * 512; t.AL0 = xhL + k * 512; t.lda0 = 4096;
          t.AH1 = hpH; t.AL1 = hpL; t.lda1 = 512;
          t.BH0 = PTH + (long)k * 262144; t.BL0 = PTL + (long)k * 262144; t.ldb0 = 512;
          t.BH1 = GTH + (long)(k - 1) * 262144; t.BL1 = GTL + (long)(k - 1) * 262144; t.ldb1 = 512;
          t.CH = actH; t.CL = actL; t.ldc = 512;
          t.kChunks = 32; t.kSplitCh = 16;
          t.epi = 2; t.alpha = SQ2; t.bias = b + k * 512; TCG(t, 8192, 512); }
        { TCP t = mkT();   // merged: [h_new | yh_{k-1}] in one N=1024 GEMM
          t.AH0 = actH; t.AL0 = actL; t.lda0 = 512;
          t.BH0 = PmH + (long)k * 262144; t.BL0 = PmL + (long)k * 262144; t.ldb0 = 512;
          if (k == 7) { t.CH = yhH + 3584; t.CL = yhL + 3584; t.ldc = 4096; }
          else        { t.CH = hnH; t.CL = hnL; t.ldc = 512; }
          t.epi = 3; t.S1H = xhH + k * 512; t.S1L = xhL + k * 512; t.ld1 = 4096;
          t.nSplit = 512;
          t.BH1 = GsH + (long)(k - 1) * 262144; t.BL1 = GsL + (long)(k - 1) * 262144; t.ldb1 = 512;
          t.CHB = yhH + (k - 1) * 512; t.CLB = yhL + (k - 1) * 512; t.ldcB = 4096;
          t.epiB = 4; t.S1BH = hpH; t.S1BL = hpL; t.ld1B = 512;
          t.kChunks = 16; t.kSplitCh = 16;
          t.alpha = SQ2; TCG(t, 8192, 1024); }
    }

    { TCP t = mkT();   // out = 0.5*SQG * yh @ Q + 5.05 * x + by
      t.AH0 = yhH; t.AL0 = yhL; t.lda0 = 4096;
      t.BH0 = QmTH; t.BL0 = QmTL; t.ldb0 = 4096;
      t.C = out; t.ldc = 1024;
      t.kChunks = 128; t.kSplitCh = 128;
      t.epi = 5; t.alpha = 0.5f * SQG; t.c1 = 0.5f * (0.1f + 10.0f);
      t.S1 = x; t.ld1 = 1024; t.bias = by; TCG(t, 8192, 1024); }
}

// round 16
// speedup vs baseline: 1.0512x; 1.0512x over previous
#include <cuda_runtime.h>
#include <cuda_bf16.h>
#include <math.h>
#include <stdint.h>

#define SQG 3.1464265445104548f   /* sqrt(NU-MU)=sqrt(9.9) */
#define SQ2 1.4142135623730951f
typedef __nv_bfloat16 bf16;

// ==================== device scratch ====================
__device__ float g_scale[9];
__device__ float g_part[9 * 64];
__device__ float g_Aq[2 * 1024 * 1024];   // two split-K planes
__device__ float g_Wq[1024 * 1024];
__device__ float g_Ar[7 * 512 * 512];
__device__ float g_Wr[8 * 512 * 512];
__device__ float g_CpanQ[1024 * 64];
__device__ float g_TQ[64 * 1024];
__device__ float g_CpanR[8 * 512 * 64];
__device__ float g_TR[8 * 64 * 512];
__device__ float g_Qm[4096 * 1024];
__device__ float g_Pm[8 * 512 * 512];
__device__ float g_Gs[7 * 512 * 512];
// bf16 hi/lo pairs
__device__ __align__(16) bf16 g_VTH[1024 * 3072],  g_VTL[1024 * 3072];
__device__ __align__(16) bf16 g_VH[3072 * 1024],   g_VL[3072 * 1024];
__device__ __align__(16) bf16 g_B2H[7 * 262144],   g_B2L[7 * 262144];
__device__ __align__(16) bf16 g_B2TH[7 * 262144],  g_B2TL[7 * 262144];
__device__ __align__(16) bf16 g_WqH[1024 * 1024],  g_WqL[1024 * 1024];
__device__ __align__(16) bf16 g_WqTH[1024 * 1024], g_WqTL[1024 * 1024];
__device__ __align__(16) bf16 g_WrH[8 * 262144],   g_WrL[8 * 262144];
__device__ __align__(16) bf16 g_WrTH[8 * 262144],  g_WrTL[8 * 262144];
__device__ __align__(16) bf16 g_ImAqTH[1024 * 1024], g_ImAqTL[1024 * 1024];
__device__ __align__(16) bf16 g_ImArTH[8 * 262144],  g_ImArTL[8 * 262144];
__device__ __align__(16) bf16 g_QmH[4096 * 1024],  g_QmL[4096 * 1024];
__device__ __align__(16) bf16 g_QmTH[1024 * 4096], g_QmTL[1024 * 4096];
__device__ __align__(16) bf16 g_PmH[8 * 262144],   g_PmL[8 * 262144];
__device__ __align__(16) bf16 g_PTH[8 * 262144],   g_PTL[8 * 262144];
__device__ __align__(16) bf16 g_GsH[7 * 262144],   g_GsL[7 * 262144];
__device__ __align__(16) bf16 g_GTH[7 * 262144],   g_GTL[7 * 262144];
__device__ __align__(16) bf16 g_xH[8192u * 1024u], g_xL[8192u * 1024u];
__device__ __align__(16) bf16 g_xhH[8192u * 4096u], g_xhL[8192u * 4096u];
__device__ __align__(16) bf16 g_actH[8192u * 512u], g_actL[8192u * 512u];
__device__ __align__(16) bf16 g_h0H[8192u * 512u],  g_h0L[8192u * 512u];
__device__ __align__(16) bf16 g_h1H[8192u * 512u],  g_h1L[8192u * 512u];
__device__ __align__(16) bf16 g_yhH[8192u * 4096u], g_yhL[8192u * 4096u];

// ==================== reductions ====================
__global__ void red_in(const float* Fq, const float* Fr0, const float* Frr) {
    __shared__ float sh[256];
    int z = blockIdx.y;
    const float* p; long n;
    if (z == 0)      { p = Fq;  n = 4096L * 1024; }
    else if (z == 1) { p = Fr0; n = 512L * 512; }
    else             { p = Frr + (long)(z - 2) * 512 * 1024; n = 512L * 1024; }
    float s = 0.f;
    for (long i = (long)blockIdx.x * 256 + threadIdx.x; i < n; i += 64L * 256) {
        float v = p[i]; s += v * v;
    }
    sh[threadIdx.x] = s; __syncthreads();
    for (int o = 128; o > 0; o >>= 1) {
        if (threadIdx.x < o) sh[threadIdx.x] += sh[threadIdx.x + o];
        __syncthreads();
    }
    if (threadIdx.x == 0) g_part[z * 64 + blockIdx.x] = sh[0];
}
__global__ void red_in_fin(const float* fq, const float* fr) {
    int t = threadIdx.x;
    if (t < 9) {
        float s = 0.f;
        for (int i = 0; i < 64; i++) s += g_part[t * 64 + i];
        float f = (t == 0) ? fq[0] : fr[t - 1];
        g_scale[t] = f / (sqrtf(s) + 1e-5f);
    }
}

// ==================== conversion kernels ====================
__device__ __forceinline__ void split_bf(float v, bf16& h, bf16& l) {
    h = __float2bfloat16_rn(v);
    l = __float2bfloat16_rn(v - __bfloat162float(h));
}
__global__ void cvt_k(const float* src, int ldS, long sS,
                      bf16* hi, bf16* lo, int ldD, long sD) {
    int z = blockIdx.z;
    src += (long)z * sS; hi += (long)z * sD; lo += (long)z * sD;
    int r = blockIdx.y, c = blockIdx.x * 256 + threadIdx.x;
    bf16 h, l;
    split_bf(src[(long)r * ldS + c], h, l);
    hi[(long)r * ldD + c] = h;
    lo[(long)r * ldD + c] = l;
}
__global__ void tr_cvt(const float* src, int ldS, long sS,
                       bf16* hi, bf16* lo, int ldD, long sD) {
    int z = blockIdx.z;
    src += (long)z * sS; hi += (long)z * sD; lo += (long)z * sD;
    __shared__ float t[32][33];
    int r0 = blockIdx.y * 32, c0 = blockIdx.x * 32;
    int tx = threadIdx.x & 31, ty = threadIdx.x >> 5;
    for (int i = ty; i < 32; i += 8) t[i][tx] = src[(long)(r0 + i) * ldS + c0 + tx];
    __syncthreads();
    for (int i = ty; i < 32; i += 8) {
        bf16 h, l;
        split_bf(t[tx][i], h, l);
        hi[(long)(c0 + i) * ldD + r0 + tx] = h;
        lo[(long)(c0 + i) * ldD + r0 + tx] = l;
    }
}

// ==================== elementwise prep ====================
__global__ void prepQ(const float* Fq) {
    int e = blockIdx.x * 256 + threadIdx.x;
    int i = e >> 10, j = e & 1023;
    float s = g_scale[0];
    float a = g_Aq[e] + g_Aq[e + 1048576]
            + s * (Fq[i * 1024 + j] - Fq[j * 1024 + i]);
    float d = (i == j) ? 1.f : 0.f;
    g_Wq[e] = d + a;
    bf16 h, l;
    split_bf(d - a, h, l);
    g_ImAqTH[j * 1024 + i] = h;
    g_ImAqTL[j * 1024 + i] = l;
}
__global__ void prepR(const float* Fr0, const float* Frr) {
    int e = blockIdx.x * 256 + threadIdx.x;
    int z = e >> 18; int r = e & 262143;
    int i = r >> 9, j = r & 511;
    float a;
    if (z == 0) {
        float s = g_scale[1];
        a = s * (Fr0[i * 512 + j] - Fr0[j * 512 + i]);
    } else {
        float s = g_scale[1 + z];
        const float* B = Frr + (long)(z - 1) * 524288;
        a = g_Ar[(long)(z - 1) * 262144 + r] + s * (B[j * 1024 + i] - B[i * 1024 + j]);
    }
    float d = (i == j) ? 1.f : 0.f;
    g_Wr[e] = d + a;
    bf16 h, l;
    split_bf(d - a, h, l);
    g_ImArTH[z * 262144 + j * 512 + i] = h;
    g_ImArTL[z * 262144 + j * 512 + i] = l;
}

// ==================== blocked in-place Gauss-Jordan (block 64) ====================
__device__ void gj_rowx_body(const float* W, int n, int s, int jb,
                             float* T, float* Cpan) {
    int t = threadIdx.x;
    for (int e = t; e < 4096; e += 256) {
        int i = e >> 6, c = e & 63;
        Cpan[(long)(jb * 64 + i) * 64 + c] = W[(long)(jb * 64 + i) * n + s * 64 + c];
    }
    __shared__ float sh[64][65];
    __shared__ float shW[64][65];
    for (int e = t; e < 4096; e += 256) {
        int i = e >> 6, j = e & 63;
        sh[i][j] = W[(long)(s * 64 + i) * n + s * 64 + j];
        if (jb != s)
            shW[i][j] = W[(long)(s * 64 + i) * n + jb * 64 + j];
    }
    __syncthreads();
    int jc = t & 63, rb = (t >> 6) * 16;
    for (int p = 0; p < 64; p++) {
        float d = 1.0f / sh[p][p];
        float c[16];
#pragma unroll
        for (int r = 0; r < 16; r++) c[r] = sh[rb + r][p];
        float pv = sh[p][jc];
        __syncthreads();
        float npv = (jc == p) ? d : pv * d;
#pragma unroll
        for (int r = 0; r < 16; r++) {
            int i = rb + r;
            if (i == p)       sh[i][jc] = npv;
            else if (jc == p) sh[i][jc] = -c[r] * d;
            else              sh[i][jc] = sh[i][jc] - c[r] * npv;
        }
        __syncthreads();
    }
    if (jb == s) {
        for (int e = t; e < 4096; e += 256)
            T[(long)(e >> 6) * n + s * 64 + (e & 63)] = sh[e >> 6][e & 63];
        return;
    }
    float acc[16];
#pragma unroll
    for (int r = 0; r < 16; r++) acc[r] = 0.f;
    for (int k = 0; k < 64; k++) {
        float bv = shW[k][jc];
#pragma unroll
        for (int r = 0; r < 16; r++) acc[r] = fmaf(sh[rb + r][k], bv, acc[r]);
    }
#pragma unroll
    for (int r = 0; r < 16; r++)
        T[(long)(rb + r) * n + jb * 64 + jc] = acc[r];
}
__device__ void gj_upd_body(float* W, int n, int s, int jb, int ib,
                            const float* Cpan, const float* T) {
    int t = threadIdx.x;
    if (ib == s) {
        for (int e = t; e < 4096; e += 256) {
            int i = e >> 6, j = e & 63;
            W[(long)(s * 64 + i) * n + jb * 64 + j] = T[(long)i * n + jb * 64 + j];
        }
        return;
    }
    __shared__ float shC[64][65], shT[64][65];
    for (int e = t; e < 4096; e += 256) {
        int i = e >> 6, j = e & 63;
        shC[i][j] = Cpan[(long)(ib * 64 + i) * 64 + j];
        shT[i][j] = T[(long)i * n + jb * 64 + j];
    }
    __syncthreads();
    int jc = t & 63, rb = (t >> 6) * 16;
    float acc[16];
#pragma unroll
    for (int r = 0; r < 16; r++) acc[r] = 0.f;
    for (int k = 0; k < 64; k++) {
        float tv = shT[k][jc];
#pragma unroll
        for (int r = 0; r < 16; r++) acc[r] = fmaf(shC[rb + r][k], tv, acc[r]);
    }
#pragma unroll
    for (int r = 0; r < 16; r++) {
        long idx = (long)(ib * 64 + rb + r) * n + jb * 64 + jc;
        float oldv = (jb == s) ? 0.f : W[idx];
        W[idx] = oldv - acc[r];
    }
}
__global__ void cgj_rowx(const float* WQ, const float* WR, int s,
                         float* TQp, float* TRp, float* CQ, float* CR) {
    int z = blockIdx.y, jb = blockIdx.x;
    if (z == 0) { gj_rowx_body(WQ, 1024, s, jb, TQp, CQ); return; }
    if (s >= 8 || jb >= 8) return;
    gj_rowx_body(WR + (long)(z - 1) * 262144, 512, s, jb,
                 TRp + (long)(z - 1) * 32768, CR + (long)(z - 1) * 32768);
}
__global__ void cgj_upd(float* WQ, float* WR, int s,
                        const float* CQ, const float* CR,
                        const float* TQp, const float* TRp) {
    int z = blockIdx.z, jb = blockIdx.x, ib = blockIdx.y;
    if (z == 0) { gj_upd_body(WQ, 1024, s, jb, ib, CQ, TQp); return; }
    if (s >= 8 || jb >= 8 || ib >= 8) return;
    gj_upd_body(WR + (long)(z - 1) * 262144, 512, s, jb, ib,
                CR + (long)(z - 1) * 32768, TRp + (long)(z - 1) * 32768);
}

// ==================== mma.sync bf16 GEMM (3-stage, swizzled smem) ============
struct TCP {
    const bf16 *AH0, *AL0, *AH1, *AL1, *BH0, *BL0, *BH1, *BL1;
    const float *S1, *bias;
    const bf16 *S1H, *S1L;
    float* C;
    bf16 *CH, *CL;
    int lda0, lda1, ldb0, ldb1, ldc, ld1;
    long sA, sB, sC;
    int kChunks, kSplitCh;
    int epi;                    // 0 plain | 2 relu+bias | 3 -S1 | 4 S1- | 5 final
    int sIdx, sStride, sPow;
    float alpha, c1;
    int nSplit;
    int epiB, ld1B, ldcB;
    const float* S1B;
    const bf16 *S1BH, *S1BL;
    float* CB;
    bf16 *CHB, *CLB;
};
#define MM_STAGE 32768
#define MM_SMEM (3 * MM_STAGE)   /* 98304 */

__device__ __forceinline__ uint32_t smem_u32(const void* p) {
    uint32_t a;
    asm("{ .reg .u64 t; cvta.to.shared.u64 t, %1; cvt.u32.u64 %0, t; }"
        : "=r"(a) : "l"(p));
    return a;
}
__device__ __forceinline__ uint32_t swz(int row, int col) {
    return (uint32_t)((row << 6) + ((((col >> 3) ^ ((row >> 1) & 3)) << 4)));
}
__device__ __forceinline__ void cp16(uint32_t s, const void* g) {
    asm volatile("cp.async.cg.shared.global [%0], [%1], 16;" :: "r"(s), "l"(g));
}
__device__ __forceinline__ void cp_commit() {
    asm volatile("cp.async.commit_group;");
}
template <int N>
__device__ __forceinline__ void cp_wait() {
    asm volatile("cp.async.wait_group %0;" :: "n"(N));
}
__device__ __forceinline__ void ldsm4(uint32_t* r, uint32_t addr) {
    asm volatile("ldmatrix.sync.aligned.m8n8.x4.shared.b16 {%0,%1,%2,%3}, [%4];"
        : "=r"(r[0]), "=r"(r[1]), "=r"(r[2]), "=r"(r[3]) : "r"(addr));
}
__device__ __forceinline__ void mma_bf16(float* d, const uint32_t* a, const uint32_t* b) {
    asm volatile(
        "mma.sync.aligned.m16n8k16.row.col.f32.bf16.bf16.f32 "
        "{%0,%1,%2,%3},{%4,%5,%6,%7},{%8,%9},{%0,%1,%2,%3};"
        : "+f"(d[0]), "+f"(d[1]), "+f"(d[2]), "+f"(d[3])
        : "r"(a[0]), "r"(a[1]), "r"(a[2]), "r"(a[3]), "r"(b[0]), "r"(b[1]));
}
__device__ __forceinline__ float s1_pair(const bf16* H, const bf16* L, long off,
                                         float& v1out) {
    uint32_t hw = *(const uint32_t*)(H + off);
    uint32_t lw = *(const uint32_t*)(L + off);
    __nv_bfloat162 hb = *(__nv_bfloat162*)&hw;
    __nv_bfloat162 lb = *(__nv_bfloat162*)&lw;
    v1out = __bfloat162float(hb.y) + __bfloat162float(lb.y);
    return __bfloat162float(hb.x) + __bfloat162float(lb.x);
}

__global__ void __launch_bounds__(256, 2) mma_gemm(TCP p) {
    extern __shared__ bf16 sm[];
    uint32_t sbase = smem_u32(sm);
    int tid = threadIdx.x, lane = tid & 31, wid = tid >> 5;
    int wm = wid & 3, wn = wid >> 2;
    int bm = blockIdx.y * 128, bn = blockIdx.x * 128;
    int z = blockIdx.z;
    const bf16* AH0z = p.AH0 + (long)z * p.sA;
    const bf16* AL0z = p.AL0 + (long)z * p.sA;

    const bf16* BH = p.BH0 + (long)z * p.sB;
    const bf16* BL = p.BL0 + (long)z * p.sB;
    int ldbN = p.ldb0;
    int bnB = bn;
    int half2 = 0;
    if (p.nSplit > 0 && bn >= p.nSplit) {
        half2 = 1; bnB = bn - p.nSplit;
        BH = p.BH1; BL = p.BL1; ldbN = p.ldb1;
    }

    float acc[2][8][4];
#pragma unroll
    for (int i = 0; i < 2; i++)
#pragma unroll
        for (int j = 0; j < 8; j++)
#pragma unroll
            for (int q = 0; q < 4; q++) acc[i][j][q] = 0.f;

    auto gissue = [&](int c, int stg) {
        const bf16 *Ah, *Al, *Bh, *Bl; int lda, ldb2, kk, kb;
        if (c < p.kSplitCh) {
            Ah = AH0z; Al = AL0z; lda = p.lda0; kk = c * 32;
            Bh = BH; Bl = BL; ldb2 = ldbN; kb = c * 32;
        } else {
            Ah = p.AH1; Al = p.AL1; lda = p.lda1; kk = (c - p.kSplitCh) * 32;
            Bh = p.BH1; Bl = p.BL1; ldb2 = p.ldb1; kb = kk;
        }
        uint32_t s0 = sbase + stg * MM_STAGE;
#pragma unroll
        for (int j = 0; j < 8; j++) {
            int li = tid + 256 * j;
            int m = li >> 9;
            int idx = li & 511;
            int row = idx >> 2, co = (idx & 3) << 3;
            const bf16* g;
            if (m == 0)      g = Ah + (long)(bm + row) * lda + kk + co;
            else if (m == 1) g = Al + (long)(bm + row) * lda + kk + co;
            else if (m == 2) g = Bh + (long)(bnB + row) * ldb2 + kb + co;
            else             g = Bl + (long)(bnB + row) * ldb2 + kb + co;
            cp16(s0 + m * 8192 + swz(row, co), g);
        }
        cp_commit();
    };
    auto compute = [&](int stg) {
        uint32_t s0 = sbase + stg * MM_STAGE;
        int arow = wm * 32 + (lane & 15);
        int acol = (lane >> 4) << 3;
        int brow = wn * 64 + (lane & 7) + ((lane & 16) >> 1);
        int bcol = lane & 8;
#pragma unroll
        for (int ks = 0; ks < 2; ks++) {
            int kc = ks * 16;
            // phase 0a: ldsm Ahi + Bhi only (6 ldsm) -> enables hh phase ASAP
            uint32_t Ahf[2][4], Alf[2][4];
            uint32_t Bhf[4][4], Blf[4][4];
#pragma unroll
            for (int mt = 0; mt < 2; mt++)
                ldsm4(Ahf[mt], s0 + swz(arow + mt * 16, kc + acol));
#pragma unroll
            for (int g = 0; g < 4; g++)
                ldsm4(Bhf[g], s0 + 16384 + swz(brow + g * 16, kc + bcol));
            // phase 1: all hh (16 independent MMAs)
#pragma unroll
            for (int mt = 0; mt < 2; mt++)
#pragma unroll
                for (int nt = 0; nt < 8; nt++)
                    mma_bf16(acc[mt][nt], Ahf[mt], &Bhf[nt >> 1][(nt & 1) * 2]);
            // phase 0b: ldsm Blo (4) — issued while hh MMAs drain
#pragma unroll
            for (int g = 0; g < 4; g++)
                ldsm4(Blf[g], s0 + 24576 + swz(brow + g * 16, kc + bcol));
            // phase 2: all hl
#pragma unroll
            for (int mt = 0; mt < 2; mt++)
#pragma unroll
                for (int nt = 0; nt < 8; nt++)
                    mma_bf16(acc[mt][nt], Ahf[mt], &Blf[nt >> 1][(nt & 1) * 2]);
            // phase 0c: ldsm Alo (2) — issued while hl MMAs drain
#pragma unroll
            for (int mt = 0; mt < 2; mt++)
                ldsm4(Alf[mt], s0 + 8192 + swz(arow + mt * 16, kc + acol));
            // phase 3: all lh
#pragma unroll
            for (int mt = 0; mt < 2; mt++)
#pragma unroll
                for (int nt = 0; nt < 8; nt++)
                    mma_bf16(acc[mt][nt], Alf[mt], &Bhf[nt >> 1][(nt & 1) * 2]);
        }
    };

    gissue(0, 0);
    if (p.kChunks > 1) gissue(1, 1);
    for (int c = 0; c < p.kChunks; ++c) {
        if (c + 1 < p.kChunks) cp_wait<1>(); else cp_wait<0>();
        __syncthreads();
        if (c + 2 < p.kChunks) gissue(c + 2, (c + 2) % 3);
        compute(c % 3);
    }

    float al = p.alpha;
    if (p.sIdx >= 0) {
        float s = g_scale[p.sIdx + z * p.sStride];
        al *= (p.sPow == 2) ? s * s : s;
    }
    int epi = half2 ? p.epiB : p.epi;
    int ld1 = half2 ? p.ld1B : p.ld1;
    int ldc = half2 ? p.ldcB : p.ldc;
    const float* S1F = half2 ? p.S1B : p.S1;
    const bf16* S1H = half2 ? p.S1BH : p.S1H;
    const bf16* S1L = half2 ? p.S1BL : p.S1L;
    float* Cz  = half2 ? p.CB  : (p.C  ? p.C  + (long)z * p.sC : (float*)0);
    bf16* CHz  = half2 ? p.CHB : (p.CH ? p.CH + (long)z * p.sC : (bf16*)0);
    bf16* CLz  = half2 ? p.CLB : (p.CL ? p.CL + (long)z * p.sC : (bf16*)0);
    int nOff = half2 ? p.nSplit : 0;
#pragma unroll
    for (int mt = 0; mt < 2; mt++) {
#pragma unroll
        for (int nt = 0; nt < 8; nt++) {
            int r0 = bm + wm * 32 + mt * 16 + (lane >> 2);
            int c0 = bn + wn * 64 + nt * 8 + (lane & 3) * 2 - nOff;
#pragma unroll
            for (int h = 0; h < 2; h++) {
                int r = r0 + h * 8;
                float v0 = al * acc[mt][nt][h * 2 + 0];
                float v1 = al * acc[mt][nt][h * 2 + 1];
                if (epi == 2) {
                    v0 = fmaxf(v0 + p.bias[c0], 0.f);
                    v1 = fmaxf(v1 + p.bias[c0 + 1], 0.f);
                } else if (epi == 3) {
                    float s1b, s1a = s1_pair(S1H, S1L, (long)r * ld1 + c0, s1b);
                    v0 -= s1a; v1 -= s1b;
                } else if (epi == 4) {
                    float s1b, s1a = s1_pair(S1H, S1L, (long)r * ld1 + c0, s1b);
                    v0 = s1a - v0; v1 = s1b - v1;
                } else if (epi == 5) {
                    v0 = v0 + p.c1 * S1F[(long)r * ld1 + c0] + p.bias[c0];
                    v1 = v1 + p.c1 * S1F[(long)r * ld1 + c0 + 1] + p.bias[c0 + 1];
                }
                if (Cz) {
                    float2 o; o.x = v0; o.y = v1;
                    *(float2*)(Cz + (long)r * ldc + c0) = o;
                }
                if (CHz) {
                    __nv_bfloat162 hh = __floats2bfloat162_rn(v0, v1);
                    float rx = v0 - __bfloat162float(hh.x);
                    float ry = v1 - __bfloat162float(hh.y);
                    __nv_bfloat162 ll = __floats2bfloat162_rn(rx, ry);
                    *(uint32_t*)(CHz + (long)r * ldc + c0) = *(uint32_t*)&hh;
                    *(uint32_t*)(CLz + (long)r * ldc + c0) = *(uint32_t*)&ll;
                }
            }
        }
    }
}

// ==================== host ====================
static TCP mkT() {
    TCP t; memset(&t, 0, sizeof(t));
    t.sIdx = -1; t.alpha = 1.f;
    return t;
}
static void TCG(const TCP& p, int M, int N, int batch = 1) {
    dim3 g(N / 128, M / 128, batch);
    mma_gemm<<<g, 256, MM_SMEM>>>(p);
}
static float* sym(const void* s) {
    void* ptr = nullptr;
    cudaGetSymbolAddress(&ptr, s);
    return (float*)ptr;
}
static bf16* symb(const void* s) {
    void* ptr = nullptr;
    cudaGetSymbolAddress(&ptr, s);
    return (bf16*)ptr;
}

extern "C" void kernel_launch(void* const* d_in, const int* in_sizes, int n_in,
                              void* d_out, int out_size) {
    const float* x   = (const float*)d_in[0];
    const float* Fq  = (const float*)d_in[1];
    const float* fq  = (const float*)d_in[2];
    const float* by  = (const float*)d_in[3];
    const float* Fr0 = (const float*)d_in[4];
    const float* Frr = (const float*)d_in[5];
    const float* fr  = (const float*)d_in[6];
    const float* b   = (const float*)d_in[7];
    float* out = (float*)d_out;

    cudaFuncSetAttribute(mma_gemm, cudaFuncAttributeMaxDynamicSharedMemorySize, MM_SMEM);

    float* Aq  = sym(g_Aq);   float* Wq  = sym(g_Wq);
    float* Arr = sym(g_Ar);   float* Wr  = sym(g_Wr);
    float* CpanQ = sym(g_CpanQ); float* TQ = sym(g_TQ);
    float* CpanR = sym(g_CpanR); float* TR = sym(g_TR);
    float* Qm = sym(g_Qm); float* Pm = sym(g_Pm); float* Gsm = sym(g_Gs);
    bf16 *VTH = symb(g_VTH), *VTL = symb(g_VTL), *VH = symb(g_VH), *VL = symb(g_VL);
    bf16 *B2H = symb(g_B2H), *B2L = symb(g_B2L), *B2TH = symb(g_B2TH), *B2TL = symb(g_B2TL);
    bf16 *WqH = symb(g_WqH), *WqL = symb(g_WqL), *WqTH = symb(g_WqTH), *WqTL = symb(g_WqTL);
    bf16 *WrH = symb(g_WrH), *WrL = symb(g_WrL), *WrTH = symb(g_WrTH), *WrTL = symb(g_WrTL);
    bf16 *ImAqTH = symb(g_ImAqTH), *ImAqTL = symb(g_ImAqTL);
    bf16 *ImArTH = symb(g_ImArTH), *ImArTL = symb(g_ImArTL);
    bf16 *QmH = symb(g_QmH), *QmL = symb(g_QmL), *QmTH = symb(g_QmTH), *QmTL = symb(g_QmTL);
    bf16 *PmH = symb(g_PmH), *PmL = symb(g_PmL), *PTH = symb(g_PTH), *PTL = symb(g_PTL);
    bf16 *GsH = symb(g_GsH), *GsL = symb(g_GsL), *GTH = symb(g_GTH), *GTL = symb(g_GTL);
    bf16 *xH = symb(g_xH), *xL = symb(g_xL);
    bf16 *xhH = symb(g_xhH), *xhL = symb(g_xhL);
    bf16 *actH = symb(g_actH), *actL = symb(g_actL);
    bf16 *h0H = symb(g_h0H), *h0L = symb(g_h0L);
    bf16 *h1H = symb(g_h1H), *h1L = symb(g_h1L);
    bf16 *yhH = symb(g_yhH), *yhL = symb(g_yhL);

    // ---- scales ----
    red_in<<<dim3(64, 9), 256>>>(Fq, Fr0, Frr);
    red_in_fin<<<1, 32>>>(fq, fr);

    // ---- input conversions ----
    tr_cvt<<<dim3(32, 96), 256>>>(Fq + 1048576, 1024, 0, VTH, VTL, 3072, 0);

    // ---- Aq = s0^2 * VT @ VT' (split-K x2) ----
    { TCP t = mkT();
      t.AH0 = VTH; t.AL0 = VTL; t.lda0 = 3072; t.sA = 1536;
      t.BH0 = VTH; t.BL0 = VTL; t.ldb0 = 3072; t.sB = 1536;
      t.C = Aq; t.ldc = 1024; t.sC = 1048576;
      t.kChunks = 48; t.kSplitCh = 48;
      t.sIdx = 0; t.sStride = 0; t.sPow = 2; TCG(t, 1024, 1024, 2); }

    // ---- remaining input conversions ----
    cvt_k<<<dim3(2, 512, 7), 256>>>(Frr + 512, 1024, 524288, B2H, B2L, 512, 262144);
    tr_cvt<<<dim3(16, 16, 7), 256>>>(Frr + 512, 1024, 524288, B2TH, B2TL, 512, 262144);
    { TCP t = mkT();   // Ar_z = s^2 * B2 B2^T
      t.AH0 = B2H; t.AL0 = B2L; t.lda0 = 512; t.sA = 262144;
      t.BH0 = B2H; t.BL0 = B2L; t.ldb0 = 512; t.sB = 262144;
      t.C = Arr; t.ldc = 512; t.sC = 262144; t.kChunks = 16; t.kSplitCh = 16;
      t.sIdx = 2; t.sStride = 1; t.sPow = 2; TCG(t, 512, 512, 7); }
    cvt_k<<<dim3(4, 3072), 256>>>(Fq + 1048576, 1024, 0, VH, VL, 1024, 0);
    cvt_k<<<dim3(4, 8192), 256>>>(x, 1024, 0, xH, xL, 1024, 0);

    prepQ<<<4096, 256>>>(Fq);
    prepR<<<8192, 256>>>(Fr0, Frr);

    // ---- inversions (2 launches per step) ----
    for (int s = 0; s < 16; s++) {
        cgj_rowx<<<dim3(16, 9), 256>>>(Wq, Wr, s, TQ, TR, CpanQ, CpanR);
        cgj_upd<<<dim3(16, 16, 9), 256>>>(Wq, Wr, s, CpanQ, CpanR, TQ, TR);
    }
    cvt_k<<<dim3(4, 1024), 256>>>(Wq, 1024, 0, WqH, WqL, 1024, 0);
    tr_cvt<<<dim3(32, 32), 256>>>(Wq, 1024, 0, WqTH, WqTL, 1024, 0);
    cvt_k<<<dim3(2, 512, 8), 256>>>(Wr, 512, 262144, WrH, WrL, 512, 262144);
    tr_cvt<<<dim3(16, 16, 8), 256>>>(Wr, 512, 262144, WrTH, WrTL, 512, 262144);

    // ---- assemble Q / P / Gs ----
    { TCP t = mkT();   // Qm top = Winv @ (I-A)
      t.AH0 = WqH; t.AL0 = WqL; t.lda0 = 1024;
      t.BH0 = ImAqTH; t.BL0 = ImAqTL; t.ldb0 = 1024;
      t.C = Qm; t.CH = QmH; t.CL = QmL; t.ldc = 1024;
      t.kChunks = 32; t.kSplitCh = 32; TCG(t, 1024, 1024); }
    { TCP t = mkT();   // Qm bottom = -2 s0 * V @ Winv
      t.AH0 = VH; t.AL0 = VL; t.lda0 = 1024;
      t.BH0 = WqTH; t.BL0 = WqTL; t.ldb0 = 1024;
      t.C = Qm + 1048576; t.CH = QmH + 1048576; t.CL = QmL + 1048576; t.ldc = 1024;
      t.kChunks = 32; t.kSplitCh = 32;
      t.sIdx = 0; t.sStride = 0; t.sPow = 1; t.alpha = -2.f; TCG(t, 3072, 1024); }
    { TCP t = mkT();   // P_z = Winv_z @ (I-A_z)
      t.AH0 = WrH; t.AL0 = WrL; t.lda0 = 512; t.sA = 262144;
      t.BH0 = ImArTH; t.BL0 = ImArTL; t.ldb0 = 512; t.sB = 262144;
      t.C = Pm; t.CH = PmH; t.CL = PmL; t.ldc = 512; t.sC = 262144;
      t.kChunks = 16; t.kSplitCh = 16; TCG(t, 512, 512, 8); }
    { TCP t = mkT();   // Gs_z = -2 s * B2^T @ Winv_{z+1}
      t.AH0 = B2TH; t.AL0 = B2TL; t.lda0 = 512; t.sA = 262144;
      t.BH0 = WrTH + 262144; t.BL0 = WrTL + 262144; t.ldb0 = 512; t.sB = 262144;
      t.C = Gsm; t.CH = GsH; t.CL = GsL; t.ldc = 512; t.sC = 262144;
      t.kChunks = 16; t.kSplitCh = 16;
      t.sIdx = 2; t.sStride = 1; t.sPow = 1; t.alpha = -2.f; TCG(t, 512, 512, 7); }

    tr_cvt<<<dim3(32, 128), 256>>>(Qm, 1024, 0, QmTH, QmTL, 4096, 0);
    tr_cvt<<<dim3(16, 16, 8), 256>>>(Pm, 512, 262144, PTH, PTL, 512, 262144);
    tr_cvt<<<dim3(16, 16, 7), 256>>>(Gsm, 512, 262144, GTH, GTL, 512, 262144);

    // ---- forward pass ----
    { TCP t = mkT();   // xh = SQG * x @ Q^T
      t.AH0 = xH; t.AL0 = xL; t.lda0 = 1024;
      t.BH0 = QmH; t.BL0 = QmL; t.ldb0 = 1024;
      t.CH = xhH; t.CL = xhL; t.ldc = 4096;
      t.kChunks = 32; t.kSplitCh = 32;
      t.epi = 0; t.alpha = SQG; TCG(t, 8192, 4096); }
    { TCP t = mkT();   // act = relu(SQ2 * xk @ P0' + b0)
      t.AH0 = xhH; t.AL0 = xhL; t.lda0 = 4096;
      t.BH0 = PmH; t.BL0 = PmL; t.ldb0 = 512;
      t.CH = actH; t.CL = actL; t.ldc = 512;
      t.kChunks = 16; t.kSplitCh = 16;
      t.epi = 2; t.alpha = SQ2; t.bias = b; TCG(t, 8192, 512); }
    { TCP t = mkT();   // h0 = SQ2 * act @ P0 - xk
      t.AH0 = actH; t.AL0 = actL; t.lda0 = 512;
      t.BH0 = PTH; t.BL0 = PTL; t.ldb0 = 512;
      t.CH = h0H; t.CL = h0L; t.ldc = 512;
      t.kChunks = 16; t.kSplitCh = 16;
      t.epi = 3; t.S1H = xhH; t.S1L = xhL; t.ld1 = 4096;
      t.alpha = SQ2; TCG(t, 8192, 512); }

    bf16* hbH[2] = {h0H, h1H};
    bf16* hbL[2] = {h0L, h1L};
    for (int k = 1; k < 8; k++) {
        bf16* hpH = hbH[(k + 1) & 1];
        bf16* hpL = hbL[(k + 1) & 1];
        bf16* hnH = hbH[k & 1];
        bf16* hnL = hbL[k & 1];
        { TCP t = mkT();   // pre = relu(SQ2*(xk@P' + hp@G') + bk)
          t.AH0 = xhH + k * 512; t.AL0 = xhL + k * 512; t.lda0 = 4096;
          t.AH1 = hpH; t.AL1 = hpL; t.lda1 = 512;
          t.BH0 = PTH + (long)k * 262144; t.BL0 = PTL + (long)k * 262144; t.ldb0 = 512;
          t.BH1 = GTH + (long)(k - 1) * 262144; t.BL1 = GTL + (long)(k - 1) * 262144; t.ldb1 = 512;
          t.CH = actH; t.CL = actL; t.ldc = 512;
          t.kChunks = 32; t.kSplitCh = 16;
          t.epi = 2; t.alpha = SQ2; t.bias = b + k * 512; TCG(t, 8192, 512); }
        { TCP t = mkT();   // merged: [h_new | yh_{k-1}] in one N=1024 GEMM
          t.AH0 = actH; t.AL0 = actL; t.lda0 = 512;
          t.BH0 = PmH + (long)k * 262144; t.BL0 = PmL + (long)k * 262144; t.ldb0 = 512;
          if (k == 7) { t.CH = yhH + 3584; t.CL = yhL + 3584; t.ldc = 4096; }
          else        { t.CH = hnH; t.CL = hnL; t.ldc = 512; }
          t.epi = 3; t.S1H = xhH + k * 512; t.S1L = xhL + k * 512; t.ld1 = 4096;
          t.nSplit = 512;
          t.BH1 = GsH + (long)(k - 1) * 262144; t.BL1 = GsL + (long)(k - 1) * 262144; t.ldb1 = 512;
          t.CHB = yhH + (k - 1) * 512; t.CLB = yhL + (k - 1) * 512; t.ldcB = 4096;
          t.epiB = 4; t.S1BH = hpH; t.S1BL = hpL; t.ld1B = 512;
          t.kChunks = 16; t.kSplitCh = 16;
          t.alpha = SQ2; TCG(t, 8192, 1024); }
    }

    { TCP t = mkT();   // out = 0.5*SQG * yh @ Q + 5.05 * x + by
      t.AH0 = yhH; t.AL0 = yhL; t.lda0 = 4096;
      t.BH0 = QmTH; t.BL0 = QmTL; t.ldb0 = 4096;
      t.C = out; t.ldc = 1024;
      t.kChunks = 128; t.kSplitCh = 128;
      t.epi = 5; t.alpha = 0.5f * SQG; t.c1 = 0.5f * (0.1f + 10.0f);
      t.S1 = x; t.ld1 = 1024; t.bias = by; TCG(t, 8192, 1024); }
}

// round 17
// speedup vs baseline: 1.0551x; 1.0037x over previous
#include <cuda_runtime.h>
#include <cuda_bf16.h>
#include <math.h>
#include <stdint.h>

#define SQG 3.1464265445104548f   /* sqrt(NU-MU)=sqrt(9.9) */
#define SQ2 1.4142135623730951f
typedef __nv_bfloat16 bf16;

// ==================== device scratch ====================
__device__ float g_scale[9];
__device__ float g_part[9 * 64];
__device__ float g_Aq[2 * 1024 * 1024];   // two split-K planes
__device__ float g_Wq[1024 * 1024];
__device__ float g_Ar[7 * 512 * 512];
__device__ float g_Wr[8 * 512 * 512];
__device__ float g_CpanQ[1024 * 64];
__device__ float g_TQ[64 * 1024];
__device__ float g_CpanR[8 * 512 * 64];
__device__ float g_TR[8 * 64 * 512];
__device__ float g_Qm[4096 * 1024];
__device__ float g_Pm[8 * 512 * 512];
__device__ float g_Gs[7 * 512 * 512];
// bf16 hi/lo pairs
__device__ __align__(16) bf16 g_VTH[1024 * 3072],  g_VTL[1024 * 3072];
__device__ __align__(16) bf16 g_VH[3072 * 1024],   g_VL[3072 * 1024];
__device__ __align__(16) bf16 g_B2H[7 * 262144],   g_B2L[7 * 262144];
__device__ __align__(16) bf16 g_B2TH[7 * 262144],  g_B2TL[7 * 262144];
__device__ __align__(16) bf16 g_WqH[1024 * 1024],  g_WqL[1024 * 1024];
__device__ __align__(16) bf16 g_WqTH[1024 * 1024], g_WqTL[1024 * 1024];
__device__ __align__(16) bf16 g_WrH[8 * 262144],   g_WrL[8 * 262144];
__device__ __align__(16) bf16 g_WrTH[8 * 262144],  g_WrTL[8 * 262144];
__device__ __align__(16) bf16 g_ImAqTH[1024 * 1024], g_ImAqTL[1024 * 1024];
__device__ __align__(16) bf16 g_ImArTH[8 * 262144],  g_ImArTL[8 * 262144];
__device__ __align__(16) bf16 g_QmH[4096 * 1024],  g_QmL[4096 * 1024];
__device__ __align__(16) bf16 g_QmTH[1024 * 4096], g_QmTL[1024 * 4096];
__device__ __align__(16) bf16 g_PmH[8 * 262144],   g_PmL[8 * 262144];
__device__ __align__(16) bf16 g_PTH[8 * 262144],   g_PTL[8 * 262144];
__device__ __align__(16) bf16 g_GsH[7 * 262144],   g_GsL[7 * 262144];
__device__ __align__(16) bf16 g_GTH[7 * 262144],   g_GTL[7 * 262144];
__device__ __align__(16) bf16 g_xH[8192u * 1024u], g_xL[8192u * 1024u];
__device__ __align__(16) bf16 g_xhH[8192u * 4096u], g_xhL[8192u * 4096u];
__device__ __align__(16) bf16 g_actH[8192u * 512u], g_actL[8192u * 512u];
__device__ __align__(16) bf16 g_h0H[8192u * 512u],  g_h0L[8192u * 512u];
__device__ __align__(16) bf16 g_h1H[8192u * 512u],  g_h1L[8192u * 512u];
__device__ __align__(16) bf16 g_yhH[8192u * 4096u], g_yhL[8192u * 4096u];

// ==================== reductions ====================
__global__ void red_in(const float* Fq, const float* Fr0, const float* Frr) {
    __shared__ float sh[256];
    int z = blockIdx.y;
    const float* p; long n;
    if (z == 0)      { p = Fq;  n = 4096L * 1024; }
    else if (z == 1) { p = Fr0; n = 512L * 512; }
    else             { p = Frr + (long)(z - 2) * 512 * 1024; n = 512L * 1024; }
    float s = 0.f;
    for (long i = (long)blockIdx.x * 256 + threadIdx.x; i < n; i += 64L * 256) {
        float v = p[i]; s += v * v;
    }
    sh[threadIdx.x] = s; __syncthreads();
    for (int o = 128; o > 0; o >>= 1) {
        if (threadIdx.x < o) sh[threadIdx.x] += sh[threadIdx.x + o];
        __syncthreads();
    }
    if (threadIdx.x == 0) g_part[z * 64 + blockIdx.x] = sh[0];
}
__global__ void red_in_fin(const float* fq, const float* fr) {
    int t = threadIdx.x;
    if (t < 9) {
        float s = 0.f;
        for (int i = 0; i < 64; i++) s += g_part[t * 64 + i];
        float f = (t == 0) ? fq[0] : fr[t - 1];
        g_scale[t] = f / (sqrtf(s) + 1e-5f);
    }
}

// ==================== conversion kernels ====================
__device__ __forceinline__ void split_bf(float v, bf16& h, bf16& l) {
    h = __float2bfloat16_rn(v);
    l = __float2bfloat16_rn(v - __bfloat162float(h));
}
__global__ void cvt_k(const float* src, int ldS, long sS,
                      bf16* hi, bf16* lo, int ldD, long sD) {
    int z = blockIdx.z;
    src += (long)z * sS; hi += (long)z * sD; lo += (long)z * sD;
    int r = blockIdx.y, c = blockIdx.x * 256 + threadIdx.x;
    bf16 h, l;
    split_bf(src[(long)r * ldS + c], h, l);
    hi[(long)r * ldD + c] = h;
    lo[(long)r * ldD + c] = l;
}
__global__ void tr_cvt(const float* src, int ldS, long sS,
                       bf16* hi, bf16* lo, int ldD, long sD) {
    int z = blockIdx.z;
    src += (long)z * sS; hi += (long)z * sD; lo += (long)z * sD;
    __shared__ float t[32][33];
    int r0 = blockIdx.y * 32, c0 = blockIdx.x * 32;
    int tx = threadIdx.x & 31, ty = threadIdx.x >> 5;
    for (int i = ty; i < 32; i += 8) t[i][tx] = src[(long)(r0 + i) * ldS + c0 + tx];
    __syncthreads();
    for (int i = ty; i < 32; i += 8) {
        bf16 h, l;
        split_bf(t[tx][i], h, l);
        hi[(long)(c0 + i) * ldD + r0 + tx] = h;
        lo[(long)(c0 + i) * ldD + r0 + tx] = l;
    }
}
// reads a square matrix once; writes normal hi/lo AND transposed hi/lo
__global__ void cvt_both(const float* src, int n, long sS,
                         bf16* hi, bf16* lo, bf16* hiT, bf16* loT, long sD) {
    int z = blockIdx.z;
    src += (long)z * sS;
    hi += (long)z * sD; lo += (long)z * sD;
    hiT += (long)z * sD; loT += (long)z * sD;
    __shared__ float t[32][33];
    int r0 = blockIdx.y * 32, c0 = blockIdx.x * 32;
    int tx = threadIdx.x & 31, ty = threadIdx.x >> 5;
    for (int i = ty; i < 32; i += 8) t[i][tx] = src[(long)(r0 + i) * n + c0 + tx];
    __syncthreads();
    for (int i = ty; i < 32; i += 8) {
        bf16 h, l;
        split_bf(t[i][tx], h, l);
        hi[(long)(r0 + i) * n + c0 + tx] = h;
        lo[(long)(r0 + i) * n + c0 + tx] = l;
        split_bf(t[tx][i], h, l);
        hiT[(long)(c0 + i) * n + r0 + tx] = h;
        loT[(long)(c0 + i) * n + r0 + tx] = l;
    }
}

// ==================== elementwise prep ====================
__global__ void prepQ(const float* Fq) {
    int e = blockIdx.x * 256 + threadIdx.x;
    int i = e >> 10, j = e & 1023;
    float s = g_scale[0];
    float a = g_Aq[e] + g_Aq[e + 1048576]
            + s * (Fq[i * 1024 + j] - Fq[j * 1024 + i]);
    float d = (i == j) ? 1.f : 0.f;
    g_Wq[e] = d + a;
    bf16 h, l;
    split_bf(d - a, h, l);
    g_ImAqTH[j * 1024 + i] = h;
    g_ImAqTL[j * 1024 + i] = l;
}
__global__ void prepR(const float* Fr0, const float* Frr) {
    int e = blockIdx.x * 256 + threadIdx.x;
    int z = e >> 18; int r = e & 262143;
    int i = r >> 9, j = r & 511;
    float a;
    if (z == 0) {
        float s = g_scale[1];
        a = s * (Fr0[i * 512 + j] - Fr0[j * 512 + i]);
    } else {
        float s = g_scale[1 + z];
        const float* B = Frr + (long)(z - 1) * 524288;
        a = g_Ar[(long)(z - 1) * 262144 + r] + s * (B[j * 1024 + i] - B[i * 1024 + j]);
    }
    float d = (i == j) ? 1.f : 0.f;
    g_Wr[e] = d + a;
    bf16 h, l;
    split_bf(d - a, h, l);
    g_ImArTH[z * 262144 + j * 512 + i] = h;
    g_ImArTL[z * 262144 + j * 512 + i] = l;
}

// ==================== blocked in-place Gauss-Jordan (block 64) ====================
__device__ void gj_rowx_body(const float* W, int n, int s, int jb,
                             float* T, float* Cpan) {
    int t = threadIdx.x;
    for (int e = t; e < 4096; e += 256) {
        int i = e >> 6, c = e & 63;
        Cpan[(long)(jb * 64 + i) * 64 + c] = W[(long)(jb * 64 + i) * n + s * 64 + c];
    }
    __shared__ float sh[64][65];
    __shared__ float shW[64][65];
    for (int e = t; e < 4096; e += 256) {
        int i = e >> 6, j = e & 63;
        sh[i][j] = W[(long)(s * 64 + i) * n + s * 64 + j];
        if (jb != s)
            shW[i][j] = W[(long)(s * 64 + i) * n + jb * 64 + j];
    }
    __syncthreads();
    int jc = t & 63, rb = (t >> 6) * 16;
    for (int p = 0; p < 64; p++) {
        float d = 1.0f / sh[p][p];
        float c[16];
#pragma unroll
        for (int r = 0; r < 16; r++) c[r] = sh[rb + r][p];
        float pv = sh[p][jc];
        __syncthreads();
        float npv = (jc == p) ? d : pv * d;
#pragma unroll
        for (int r = 0; r < 16; r++) {
            int i = rb + r;
            if (i == p)       sh[i][jc] = npv;
            else if (jc == p) sh[i][jc] = -c[r] * d;
            else              sh[i][jc] = sh[i][jc] - c[r] * npv;
        }
        __syncthreads();
    }
    if (jb == s) {
        for (int e = t; e < 4096; e += 256)
            T[(long)(e >> 6) * n + s * 64 + (e & 63)] = sh[e >> 6][e & 63];
        return;
    }
    float acc[16];
#pragma unroll
    for (int r = 0; r < 16; r++) acc[r] = 0.f;
    for (int k = 0; k < 64; k++) {
        float bv = shW[k][jc];
#pragma unroll
        for (int r = 0; r < 16; r++) acc[r] = fmaf(sh[rb + r][k], bv, acc[r]);
    }
#pragma unroll
    for (int r = 0; r < 16; r++)
        T[(long)(rb + r) * n + jb * 64 + jc] = acc[r];
}
__device__ void gj_upd_body(float* W, int n, int s, int jb, int ib,
                            const float* Cpan, const float* T) {
    int t = threadIdx.x;
    if (ib == s) {
        for (int e = t; e < 4096; e += 256) {
            int i = e >> 6, j = e & 63;
            W[(long)(s * 64 + i) * n + jb * 64 + j] = T[(long)i * n + jb * 64 + j];
        }
        return;
    }
    __shared__ float shC[64][65], shT[64][65];
    for (int e = t; e < 4096; e += 256) {
        int i = e >> 6, j = e & 63;
        shC[i][j] = Cpan[(long)(ib * 64 + i) * 64 + j];
        shT[i][j] = T[(long)i * n + jb * 64 + j];
    }
    __syncthreads();
    int jc = t & 63, rb = (t >> 6) * 16;
    float acc[16];
#pragma unroll
    for (int r = 0; r < 16; r++) acc[r] = 0.f;
    for (int k = 0; k < 64; k++) {
        float tv = shT[k][jc];
#pragma unroll
        for (int r = 0; r < 16; r++) acc[r] = fmaf(shC[rb + r][k], tv, acc[r]);
    }
#pragma unroll
    for (int r = 0; r < 16; r++) {
        long idx = (long)(ib * 64 + rb + r) * n + jb * 64 + jc;
        float oldv = (jb == s) ? 0.f : W[idx];
        W[idx] = oldv - acc[r];
    }
}
__global__ void cgj_rowx(const float* WQ, const float* WR, int s,
                         float* TQp, float* TRp, float* CQ, float* CR) {
    int z = blockIdx.y, jb = blockIdx.x;
    if (z == 0) { gj_rowx_body(WQ, 1024, s, jb, TQp, CQ); return; }
    if (s >= 8 || jb >= 8) return;
    gj_rowx_body(WR + (long)(z - 1) * 262144, 512, s, jb,
                 TRp + (long)(z - 1) * 32768, CR + (long)(z - 1) * 32768);
}
__global__ void cgj_upd(float* WQ, float* WR, int s,
                        const float* CQ, const float* CR,
                        const float* TQp, const float* TRp) {
    int z = blockIdx.z, jb = blockIdx.x, ib = blockIdx.y;
    if (z == 0) { gj_upd_body(WQ, 1024, s, jb, ib, CQ, TQp); return; }
    if (s >= 8 || jb >= 8 || ib >= 8) return;
    gj_upd_body(WR + (long)(z - 1) * 262144, 512, s, jb, ib,
                CR + (long)(z - 1) * 32768, TRp + (long)(z - 1) * 32768);
}

// ==================== mma.sync bf16 GEMM (3-stage, swizzled smem) ============
struct TCP {
    const bf16 *AH0, *AL0, *AH1, *AL1, *BH0, *BL0, *BH1, *BL1;
    const float *S1, *bias;
    const bf16 *S1H, *S1L;
    float* C;
    bf16 *CH, *CL;
    int lda0, lda1, ldb0, ldb1, ldc, ld1;
    long sA, sB, sC;
    int kChunks, kSplitCh;
    int epi;                    // 0 plain | 2 relu+bias | 3 -S1 | 4 S1- | 5 final
    int sIdx, sStride, sPow;
    float alpha, c1;
    int nSplit;
    int epiB, ld1B, ldcB;
    const float* S1B;
    const bf16 *S1BH, *S1BL;
    float* CB;
    bf16 *CHB, *CLB;
};
#define MM_STAGE 32768
#define MM_SMEM (3 * MM_STAGE)   /* 98304 */

__device__ __forceinline__ uint32_t smem_u32(const void* p) {
    uint32_t a;
    asm("{ .reg .u64 t; cvta.to.shared.u64 t, %1; cvt.u32.u64 %0, t; }"
        : "=r"(a) : "l"(p));
    return a;
}
__device__ __forceinline__ uint32_t swz(int row, int col) {
    return (uint32_t)((row << 6) + ((((col >> 3) ^ ((row >> 1) & 3)) << 4)));
}
__device__ __forceinline__ void cp16(uint32_t s, const void* g) {
    asm volatile("cp.async.cg.shared.global [%0], [%1], 16;" :: "r"(s), "l"(g));
}
__device__ __forceinline__ void cp_commit() {
    asm volatile("cp.async.commit_group;");
}
template <int N>
__device__ __forceinline__ void cp_wait() {
    asm volatile("cp.async.wait_group %0;" :: "n"(N));
}
__device__ __forceinline__ void ldsm4(uint32_t* r, uint32_t addr) {
    asm volatile("ldmatrix.sync.aligned.m8n8.x4.shared.b16 {%0,%1,%2,%3}, [%4];"
        : "=r"(r[0]), "=r"(r[1]), "=r"(r[2]), "=r"(r[3]) : "r"(addr));
}
__device__ __forceinline__ void mma_bf16(float* d, const uint32_t* a, const uint32_t* b) {
    asm volatile(
        "mma.sync.aligned.m16n8k16.row.col.f32.bf16.bf16.f32 "
        "{%0,%1,%2,%3},{%4,%5,%6,%7},{%8,%9},{%0,%1,%2,%3};"
        : "+f"(d[0]), "+f"(d[1]), "+f"(d[2]), "+f"(d[3])
        : "r"(a[0]), "r"(a[1]), "r"(a[2]), "r"(a[3]), "r"(b[0]), "r"(b[1]));
}
__device__ __forceinline__ float s1_pair(const bf16* H, const bf16* L, long off,
                                         float& v1out) {
    uint32_t hw = *(const uint32_t*)(H + off);
    uint32_t lw = *(const uint32_t*)(L + off);
    __nv_bfloat162 hb = *(__nv_bfloat162*)&hw;
    __nv_bfloat162 lb = *(__nv_bfloat162*)&lw;
    v1out = __bfloat162float(hb.y) + __bfloat162float(lb.y);
    return __bfloat162float(hb.x) + __bfloat162float(lb.x);
}

__global__ void __launch_bounds__(256, 2) mma_gemm(TCP p) {
    extern __shared__ bf16 sm[];
    uint32_t sbase = smem_u32(sm);
    int tid = threadIdx.x, lane = tid & 31, wid = tid >> 5;
    int wm = wid & 3, wn = wid >> 2;
    int bm = blockIdx.y * 128, bn = blockIdx.x * 128;
    int z = blockIdx.z;
    const bf16* AH0z = p.AH0 + (long)z * p.sA;
    const bf16* AL0z = p.AL0 + (long)z * p.sA;

    const bf16* BH = p.BH0 + (long)z * p.sB;
    const bf16* BL = p.BL0 + (long)z * p.sB;
    int ldbN = p.ldb0;
    int bnB = bn;
    int half2 = 0;
    if (p.nSplit > 0 && bn >= p.nSplit) {
        half2 = 1; bnB = bn - p.nSplit;
        BH = p.BH1; BL = p.BL1; ldbN = p.ldb1;
    }

    float acc[2][8][4];
#pragma unroll
    for (int i = 0; i < 2; i++)
#pragma unroll
        for (int j = 0; j < 8; j++)
#pragma unroll
            for (int q = 0; q < 4; q++) acc[i][j][q] = 0.f;

    auto gissue = [&](int c, int stg) {
        const bf16 *Ah, *Al, *Bh, *Bl; int lda, ldb2, kk, kb;
        if (c < p.kSplitCh) {
            Ah = AH0z; Al = AL0z; lda = p.lda0; kk = c * 32;
            Bh = BH; Bl = BL; ldb2 = ldbN; kb = c * 32;
        } else {
            Ah = p.AH1; Al = p.AL1; lda = p.lda1; kk = (c - p.kSplitCh) * 32;
            Bh = p.BH1; Bl = p.BL1; ldb2 = p.ldb1; kb = kk;
        }
        uint32_t s0 = sbase + stg * MM_STAGE;
#pragma unroll
        for (int j = 0; j < 8; j++) {
            int li = tid + 256 * j;
            int m = li >> 9;
            int idx = li & 511;
            int row = idx >> 2, co = (idx & 3) << 3;
            const bf16* g;
            if (m == 0)      g = Ah + (long)(bm + row) * lda + kk + co;
            else if (m == 1) g = Al + (long)(bm + row) * lda + kk + co;
            else if (m == 2) g = Bh + (long)(bnB + row) * ldb2 + kb + co;
            else             g = Bl + (long)(bnB + row) * ldb2 + kb + co;
            cp16(s0 + m * 8192 + swz(row, co), g);
        }
        cp_commit();
    };
    auto compute = [&](int stg) {
        uint32_t s0 = sbase + stg * MM_STAGE;
        int arow = wm * 32 + (lane & 15);
        int acol = (lane >> 4) << 3;
        int brow = wn * 64 + (lane & 7) + ((lane & 16) >> 1);
        int bcol = lane & 8;
#pragma unroll
        for (int ks = 0; ks < 2; ks++) {
            int kc = ks * 16;
            uint32_t Ahf[2][4], Alf[2][4];
            uint32_t Bhf[4][4], Blf[4][4];
#pragma unroll
            for (int mt = 0; mt < 2; mt++)
                ldsm4(Ahf[mt], s0 + swz(arow + mt * 16, kc + acol));
#pragma unroll
            for (int g = 0; g < 4; g++)
                ldsm4(Bhf[g], s0 + 16384 + swz(brow + g * 16, kc + bcol));
#pragma unroll
            for (int mt = 0; mt < 2; mt++)
#pragma unroll
                for (int nt = 0; nt < 8; nt++)
                    mma_bf16(acc[mt][nt], Ahf[mt], &Bhf[nt >> 1][(nt & 1) * 2]);
#pragma unroll
            for (int g = 0; g < 4; g++)
                ldsm4(Blf[g], s0 + 24576 + swz(brow + g * 16, kc + bcol));
#pragma unroll
            for (int mt = 0; mt < 2; mt++)
#pragma unroll
                for (int nt = 0; nt < 8; nt++)
                    mma_bf16(acc[mt][nt], Ahf[mt], &Blf[nt >> 1][(nt & 1) * 2]);
#pragma unroll
            for (int mt = 0; mt < 2; mt++)
                ldsm4(Alf[mt], s0 + 8192 + swz(arow + mt * 16, kc + acol));
#pragma unroll
            for (int mt = 0; mt < 2; mt++)
#pragma unroll
                for (int nt = 0; nt < 8; nt++)
                    mma_bf16(acc[mt][nt], Alf[mt], &Bhf[nt >> 1][(nt & 1) * 2]);
        }
    };

    gissue(0, 0);
    if (p.kChunks > 1) gissue(1, 1);
    for (int c = 0; c < p.kChunks; ++c) {
        if (c + 1 < p.kChunks) cp_wait<1>(); else cp_wait<0>();
        __syncthreads();
        if (c + 2 < p.kChunks) gissue(c + 2, (c + 2) % 3);
        compute(c % 3);
    }

    float al = p.alpha;
    if (p.sIdx >= 0) {
        float s = g_scale[p.sIdx + z * p.sStride];
        al *= (p.sPow == 2) ? s * s : s;
    }
    int epi = half2 ? p.epiB : p.epi;
    int ld1 = half2 ? p.ld1B : p.ld1;
    int ldc = half2 ? p.ldcB : p.ldc;
    const float* S1F = half2 ? p.S1B : p.S1;
    const bf16* S1H = half2 ? p.S1BH : p.S1H;
    const bf16* S1L = half2 ? p.S1BL : p.S1L;
    float* Cz  = half2 ? p.CB  : (p.C  ? p.C  + (long)z * p.sC : (float*)0);
    bf16* CHz  = half2 ? p.CHB : (p.CH ? p.CH + (long)z * p.sC : (bf16*)0);
    bf16* CLz  = half2 ? p.CLB : (p.CL ? p.CL + (long)z * p.sC : (bf16*)0);
    int nOff = half2 ? p.nSplit : 0;
#pragma unroll
    for (int mt = 0; mt < 2; mt++) {
#pragma unroll
        for (int nt = 0; nt < 8; nt++) {
            int r0 = bm + wm * 32 + mt * 16 + (lane >> 2);
            int c0 = bn + wn * 64 + nt * 8 + (lane & 3) * 2 - nOff;
#pragma unroll
            for (int h = 0; h < 2; h++) {
                int r = r0 + h * 8;
                float v0 = al * acc[mt][nt][h * 2 + 0];
                float v1 = al * acc[mt][nt][h * 2 + 1];
                if (epi == 2) {
                    v0 = fmaxf(v0 + p.bias[c0], 0.f);
                    v1 = fmaxf(v1 + p.bias[c0 + 1], 0.f);
                } else if (epi == 3) {
                    float s1b, s1a = s1_pair(S1H, S1L, (long)r * ld1 + c0, s1b);
                    v0 -= s1a; v1 -= s1b;
                } else if (epi == 4) {
                    float s1b, s1a = s1_pair(S1H, S1L, (long)r * ld1 + c0, s1b);
                    v0 = s1a - v0; v1 = s1b - v1;
                } else if (epi == 5) {
                    v0 = v0 + p.c1 * S1F[(long)r * ld1 + c0] + p.bias[c0];
                    v1 = v1 + p.c1 * S1F[(long)r * ld1 + c0 + 1] + p.bias[c0 + 1];
                }
                if (Cz) {
                    float2 o; o.x = v0; o.y = v1;
                    *(float2*)(Cz + (long)r * ldc + c0) = o;
                }
                if (CHz) {
                    __nv_bfloat162 hh = __floats2bfloat162_rn(v0, v1);
                    float rx = v0 - __bfloat162float(hh.x);
                    float ry = v1 - __bfloat162float(hh.y);
                    __nv_bfloat162 ll = __floats2bfloat162_rn(rx, ry);
                    *(uint32_t*)(CHz + (long)r * ldc + c0) = *(uint32_t*)&hh;
                    *(uint32_t*)(CLz + (long)r * ldc + c0) = *(uint32_t*)&ll;
                }
            }
        }
    }
}

// ==================== host ====================
static TCP mkT() {
    TCP t; memset(&t, 0, sizeof(t));
    t.sIdx = -1; t.alpha = 1.f;
    return t;
}
static void TCG(const TCP& p, int M, int N, int batch = 1) {
    dim3 g(N / 128, M / 128, batch);
    mma_gemm<<<g, 256, MM_SMEM>>>(p);
}
static float* sym(const void* s) {
    void* ptr = nullptr;
    cudaGetSymbolAddress(&ptr, s);
    return (float*)ptr;
}
static bf16* symb(const void* s) {
    void* ptr = nullptr;
    cudaGetSymbolAddress(&ptr, s);
    return (bf16*)ptr;
}

extern "C" void kernel_launch(void* const* d_in, const int* in_sizes, int n_in,
                              void* d_out, int out_size) {
    const float* x   = (const float*)d_in[0];
    const float* Fq  = (const float*)d_in[1];
    const float* fq  = (const float*)d_in[2];
    const float* by  = (const float*)d_in[3];
    const float* Fr0 = (const float*)d_in[4];
    const float* Frr = (const float*)d_in[5];
    const float* fr  = (const float*)d_in[6];
    const float* b   = (const float*)d_in[7];
    float* out = (float*)d_out;

    cudaFuncSetAttribute(mma_gemm, cudaFuncAttributeMaxDynamicSharedMemorySize, MM_SMEM);

    float* Aq  = sym(g_Aq);   float* Wq  = sym(g_Wq);
    float* Arr = sym(g_Ar);   float* Wr  = sym(g_Wr);
    float* CpanQ = sym(g_CpanQ); float* TQ = sym(g_TQ);
    float* CpanR = sym(g_CpanR); float* TR = sym(g_TR);
    float* Qm = sym(g_Qm); float* Pm = sym(g_Pm); float* Gsm = sym(g_Gs);
    bf16 *VTH = symb(g_VTH), *VTL = symb(g_VTL), *VH = symb(g_VH), *VL = symb(g_VL);
    bf16 *B2H = symb(g_B2H), *B2L = symb(g_B2L), *B2TH = symb(g_B2TH), *B2TL = symb(g_B2TL);
    bf16 *WqH = symb(g_WqH), *WqL = symb(g_WqL), *WqTH = symb(g_WqTH), *WqTL = symb(g_WqTL);
    bf16 *WrH = symb(g_WrH), *WrL = symb(g_WrL), *WrTH = symb(g_WrTH), *WrTL = symb(g_WrTL);
    bf16 *ImAqTH = symb(g_ImAqTH), *ImAqTL = symb(g_ImAqTL);
    bf16 *ImArTH = symb(g_ImArTH), *ImArTL = symb(g_ImArTL);
    bf16 *QmH = symb(g_QmH), *QmL = symb(g_QmL), *QmTH = symb(g_QmTH), *QmTL = symb(g_QmTL);
    bf16 *PmH = symb(g_PmH), *PmL = symb(g_PmL), *PTH = symb(g_PTH), *PTL = symb(g_PTL);
    bf16 *GsH = symb(g_GsH), *GsL = symb(g_GsL), *GTH = symb(g_GTH), *GTL = symb(g_GTL);
    bf16 *xH = symb(g_xH), *xL = symb(g_xL);
    bf16 *xhH = symb(g_xhH), *xhL = symb(g_xhL);
    bf16 *actH = symb(g_actH), *actL = symb(g_actL);
    bf16 *h0H = symb(g_h0H), *h0L = symb(g_h0L);
    bf16 *h1H = symb(g_h1H), *h1L = symb(g_h1L);
    bf16 *yhH = symb(g_yhH), *yhL = symb(g_yhL);

    // ---- scales ----
    red_in<<<dim3(64, 9), 256>>>(Fq, Fr0, Frr);
    red_in_fin<<<1, 32>>>(fq, fr);

    // ---- input conversions ----
    tr_cvt<<<dim3(32, 96), 256>>>(Fq + 1048576, 1024, 0, VTH, VTL, 3072, 0);

    // ---- Aq = s0^2 * VT @ VT' (split-K x2) ----
    { TCP t = mkT();
      t.AH0 = VTH; t.AL0 = VTL; t.lda0 = 3072; t.sA = 1536;
      t.BH0 = VTH; t.BL0 = VTL; t.ldb0 = 3072; t.sB = 1536;
      t.C = Aq; t.ldc = 1024; t.sC = 1048576;
      t.kChunks = 48; t.kSplitCh = 48;
      t.sIdx = 0; t.sStride = 0; t.sPow = 2; TCG(t, 1024, 1024, 2); }

    // ---- remaining input conversions ----
    cvt_k<<<dim3(2, 512, 7), 256>>>(Frr + 512, 1024, 524288, B2H, B2L, 512, 262144);
    tr_cvt<<<dim3(16, 16, 7), 256>>>(Frr + 512, 1024, 524288, B2TH, B2TL, 512, 262144);
    { TCP t = mkT();   // Ar_z = s^2 * B2 B2^T
      t.AH0 = B2H; t.AL0 = B2L; t.lda0 = 512; t.sA = 262144;
      t.BH0 = B2H; t.BL0 = B2L; t.ldb0 = 512; t.sB = 262144;
      t.C = Arr; t.ldc = 512; t.sC = 262144; t.kChunks = 16; t.kSplitCh = 16;
      t.sIdx = 2; t.sStride = 1; t.sPow = 2; TCG(t, 512, 512, 7); }
    cvt_k<<<dim3(4, 3072), 256>>>(Fq + 1048576, 1024, 0, VH, VL, 1024, 0);
    cvt_k<<<dim3(4, 8192), 256>>>(x, 1024, 0, xH, xL, 1024, 0);

    prepQ<<<4096, 256>>>(Fq);
    prepR<<<8192, 256>>>(Fr0, Frr);

    // ---- inversions (2 launches per step; grids trimmed for s>=8) ----
    for (int s = 0; s < 8; s++) {
        cgj_rowx<<<dim3(16, 9), 256>>>(Wq, Wr, s, TQ, TR, CpanQ, CpanR);
        cgj_upd<<<dim3(16, 16, 9), 256>>>(Wq, Wr, s, CpanQ, CpanR, TQ, TR);
    }
    for (int s = 8; s < 16; s++) {
        cgj_rowx<<<dim3(16, 1), 256>>>(Wq, Wr, s, TQ, TR, CpanQ, CpanR);
        cgj_upd<<<dim3(16, 16, 1), 256>>>(Wq, Wr, s, CpanQ, CpanR, TQ, TR);
    }
    // W conversions: read once, write normal + transposed hi/lo
    cvt_both<<<dim3(32, 32), 256>>>(Wq, 1024, 0, WqH, WqL, WqTH, WqTL, 0);
    cvt_both<<<dim3(16, 16, 8), 256>>>(Wr, 512, 262144, WrH, WrL, WrTH, WrTL, 262144);

    // ---- assemble Q / P / Gs ----
    { TCP t = mkT();   // Qm top = Winv @ (I-A)
      t.AH0 = WqH; t.AL0 = WqL; t.lda0 = 1024;
      t.BH0 = ImAqTH; t.BL0 = ImAqTL; t.ldb0 = 1024;
      t.C = Qm; t.CH = QmH; t.CL = QmL; t.ldc = 1024;
      t.kChunks = 32; t.kSplitCh = 32; TCG(t, 1024, 1024); }
    { TCP t = mkT();   // Qm bottom = -2 s0 * V @ Winv
      t.AH0 = VH; t.AL0 = VL; t.lda0 = 1024;
      t.BH0 = WqTH; t.BL0 = WqTL; t.ldb0 = 1024;
      t.C = Qm + 1048576; t.CH = QmH + 1048576; t.CL = QmL + 1048576; t.ldc = 1024;
      t.kChunks = 32; t.kSplitCh = 32;
      t.sIdx = 0; t.sStride = 0; t.sPow = 1; t.alpha = -2.f; TCG(t, 3072, 1024); }
    { TCP t = mkT();   // P_z = Winv_z @ (I-A_z)
      t.AH0 = WrH; t.AL0 = WrL; t.lda0 = 512; t.sA = 262144;
      t.BH0 = ImArTH; t.BL0 = ImArTL; t.ldb0 = 512; t.sB = 262144;
      t.C = Pm; t.CH = PmH; t.CL = PmL; t.ldc = 512; t.sC = 262144;
      t.kChunks = 16; t.kSplitCh = 16; TCG(t, 512, 512, 8); }
    { TCP t = mkT();   // Gs_z = -2 s * B2^T @ Winv_{z+1}
      t.AH0 = B2TH; t.AL0 = B2TL; t.lda0 = 512; t.sA = 262144;
      t.BH0 = WrTH + 262144; t.BL0 = WrTL + 262144; t.ldb0 = 512; t.sB = 262144;
      t.C = Gsm; t.CH = GsH; t.CL = GsL; t.ldc = 512; t.sC = 262144;
      t.kChunks = 16; t.kSplitCh = 16;
      t.sIdx = 2; t.sStride = 1; t.sPow = 1; t.alpha = -2.f; TCG(t, 512, 512, 7); }

    tr_cvt<<<dim3(32, 128), 256>>>(Qm, 1024, 0, QmTH, QmTL, 4096, 0);
    tr_cvt<<<dim3(16, 16, 8), 256>>>(Pm, 512, 262144, PTH, PTL, 512, 262144);
    tr_cvt<<<dim3(16, 16, 7), 256>>>(Gsm, 512, 262144, GTH, GTL, 512, 262144);

    // ---- forward pass ----
    { TCP t = mkT();   // xh = SQG * x @ Q^T
      t.AH0 = xH; t.AL0 = xL; t.lda0 = 1024;
      t.BH0 = QmH; t.BL0 = QmL; t.ldb0 = 1024;
      t.CH = xhH; t.CL = xhL; t.ldc = 4096;
      t.kChunks = 32; t.kSplitCh = 32;
      t.epi = 0; t.alpha = SQG; TCG(t, 8192, 4096); }
    { TCP t = mkT();   // act = relu(SQ2 * xk @ P0' + b0)
      t.AH0 = xhH; t.AL0 = xhL; t.lda0 = 4096;
      t.BH0 = PmH; t.BL0 = PmL; t.ldb0 = 512;
      t.CH = actH; t.CL = actL; t.ldc = 512;
      t.kChunks = 16; t.kSplitCh = 16;
      t.epi = 2; t.alpha = SQ2; t.bias = b; TCG(t, 8192, 512); }
    { TCP t = mkT();   // h0 = SQ2 * act @ P0 - xk
      t.AH0 = actH; t.AL0 = actL; t.lda0 = 512;
      t.BH0 = PTH; t.BL0 = PTL; t.ldb0 = 512;
      t.CH = h0H; t.CL = h0L; t.ldc = 512;
      t.kChunks = 16; t.kSplitCh = 16;
      t.epi = 3; t.S1H = xhH; t.S1L = xhL; t.ld1 = 4096;
      t.alpha = SQ2; TCG(t, 8192, 512); }

    bf16* hbH[2] = {h0H, h1H};
    bf16* hbL[2] = {h0L, h1L};
    for (int k = 1; k < 8; k++) {
        bf16* hpH = hbH[(k + 1) & 1];
        bf16* hpL = hbL[(k + 1) & 1];
        bf16* hnH = hbH[k & 1];
        bf16* hnL = hbL[k & 1];
        { TCP t = mkT();   // pre = relu(SQ2*(xk@P' + hp@G') + bk)
          t.AH0 = xhH + k * 512; t.AL0 = xhL + k * 512; t.lda0 = 4096;
          t.AH1 = hpH; t.AL1 = hpL; t.lda1 = 512;
          t.BH0 = PTH + (long)k * 262144; t.BL0 = PTL + (long)k * 262144; t.ldb0 = 512;
          t.BH1 = GTH + (long)(k - 1) * 262144; t.BL1 = GTL + (long)(k - 1) * 262144; t.ldb1 = 512;
          t.CH = actH; t.CL = actL; t.ldc = 512;
          t.kChunks = 32; t.kSplitCh = 16;
          t.epi = 2; t.alpha = SQ2; t.bias = b + k * 512; TCG(t, 8192, 512); }
        { TCP t = mkT();   // merged: [h_new | yh_{k-1}] in one N=1024 GEMM
          t.AH0 = actH; t.AL0 = actL; t.lda0 = 512;
          t.BH0 = PmH + (long)k * 262144; t.BL0 = PmL + (long)k * 262144; t.ldb0 = 512;
          if (k == 7) { t.CH = yhH + 3584; t.CL = yhL + 3584; t.ldc = 4096; }
          else        { t.CH = hnH; t.CL = hnL; t.ldc = 512; }
          t.epi = 3; t.S1H = xhH + k * 512; t.S1L = xhL + k * 512; t.ld1 = 4096;
          t.nSplit = 512;
          t.BH1 = GsH + (long)(k - 1) * 262144; t.BL1 = GsL + (long)(k - 1) * 262144; t.ldb1 = 512;
          t.CHB = yhH + (k - 1) * 512; t.CLB = yhL + (k - 1) * 512; t.ldcB = 4096;
          t.epiB = 4; t.S1BH = hpH; t.S1BL = hpL; t.ld1B = 512;
          t.kChunks = 16; t.kSplitCh = 16;
          t.alpha = SQ2; TCG(t, 8192, 1024); }
    }

    { TCP t = mkT();   // out = 0.5*SQG * yh @ Q + 5.05 * x + by
      t.AH0 = yhH; t.AL0 = yhL; t.lda0 = 4096;
      t.BH0 = QmTH; t.BL0 = QmTL; t.ldb0 = 4096;
      t.C = out; t.ldc = 1024;
      t.kChunks = 128; t.kSplitCh = 128;
      t.epi = 5; t.alpha = 0.5f * SQG; t.c1 = 0.5f * (0.1f + 10.0f);
      t.S1 = x; t.ld1 = 1024; t.bias = by; TCG(t, 8192, 1024); }
}